// round 12
// baseline (speedup 1.0000x reference)
#include <cuda_runtime.h>
#include <cuda_fp16.h>
#include <math.h>
#include <stdint.h>

#define BATCH 256
#define SEQ   720
#define CH    321
#define CUTF  200
#define FOUT  400

#define KD 768    // padded K stage1 (time 720; compute 736)
#define KX 448    // padded K stage2 (2*CUTF=400; compute 416)
#define KO 832    // padded K stage3 (2*FOUT=800)
#define N1 512    // padded N stage1
#define N3 768    // padded N stage3

#define RSB 80            // smem row stride bytes (32 fp16 + 16 pad)
#define TB  (128 * RSB)   // one tile: 10240 B
#define SMEM_BYTES (6 * TB)  // 2 stages x 3 tiles = 61440

typedef unsigned int u32;
typedef uint16_t u16;

// ---------------- device scratch ---------------------------------------------
__device__ __align__(256) __half d_Eh[(size_t)N1 * KD];   // twiddle hi
__device__ __align__(256) __half d_El[(size_t)N1 * KD];   // twiddle lo
__device__ __align__(256) __half d_Fh[(size_t)N3 * KO];
__device__ __align__(256) __half d_Fl[(size_t)N3 * KO];
__device__ __align__(256) __half d_xn[(size_t)CH * BATCH * KD];   // normalized input
__device__ __align__(256) __half d_X[(size_t)CH * BATCH * KX];    // DFT out (interleaved re/im)
__device__ __align__(256) __half d_O[(size_t)CH * BATCH * KO];    // mixer out
__device__ __align__(256) float d_y[(size_t)CH * BATCH * SEQ];
__device__ float d_mean[BATCH * CH];
__device__ float d_stdev[BATCH * CH];
__device__ float d_invstd[BATCH * CH];

// ---------------- helpers ----------------------------------------------------
__device__ __forceinline__ u32 s2u(const void* p) {
    u32 a;
    asm("{ .reg .u64 t; cvta.to.shared.u64 t, %1; cvt.u32.u64 %0, t; }" : "=r"(a) : "l"(p));
    return a;
}
__device__ __forceinline__ void cpa16(u32 dst, const void* src) {
    asm volatile("cp.async.ca.shared.global [%0], [%1], 16;" :: "r"(dst), "l"(src));
}
__device__ __forceinline__ void cp_commit() { asm volatile("cp.async.commit_group;"); }
__device__ __forceinline__ void cp_wait1() { asm volatile("cp.async.wait_group 1;"); }
__device__ __forceinline__ void cp_wait0() { asm volatile("cp.async.wait_group 0;"); }
__device__ __forceinline__ void ldsm4(u32 a[4], u32 addr) {
    asm volatile("ldmatrix.sync.aligned.m8n8.x4.shared.b16 {%0,%1,%2,%3}, [%4];"
                 : "=r"(a[0]), "=r"(a[1]), "=r"(a[2]), "=r"(a[3]) : "r"(addr));
}
__device__ __forceinline__ void mma16816(float c[4], const u32 a[4], u32 b0, u32 b1) {
    asm volatile(
        "mma.sync.aligned.m16n8k16.row.col.f32.f16.f16.f32 "
        "{%0,%1,%2,%3},{%4,%5,%6,%7},{%8,%9},{%0,%1,%2,%3};"
        : "+f"(c[0]), "+f"(c[1]), "+f"(c[2]), "+f"(c[3])
        : "r"(a[0]), "r"(a[1]), "r"(a[2]), "r"(a[3]), "r"(b0), "r"(b1));
}
__device__ __forceinline__ u16 f2h(float v) { return __half_as_ushort(__float2half_rn(v)); }
__device__ __forceinline__ u32 pack2(float a, float b) {
    return (u32)f2h(a) | ((u32)f2h(b) << 16);
}

// cp.async one 128x32fp16 tile (64B/row) into padded smem; 128 threads, 1 row each
__device__ __forceinline__ void cp_tile(u32 smDst, const char* gSrc, int rowStrideBytes,
                                        int kByteOff, int tid) {
    const char* s = gSrc + (size_t)tid * rowStrideBytes + kByteOff;
    u32 d = smDst + tid * RSB;
    cpa16(d, s);
    cpa16(d + 16, s + 16);
    cpa16(d + 32, s + 32);
    cpa16(d + 48, s + 48);
}

// one 32-K chunk; 4 warps (2x2), warp tile 64x64; A single, B hi+lo
__device__ __forceinline__ void compute_chunk(float acc[4][8][4], u32 a_b,
                                              u32 bh_b, u32 bl_b,
                                              int wm, int wn, int lane, int nv) {
    if (wn * 64 >= nv) return;           // whole warp dead (warp-uniform)
    const int rsel = lane & 15;
    const int kbh = (lane >> 4) * 16;
#pragma unroll
    for (int k16 = 0; k16 < 2; k16++) {
        const int kb = k16 * 32 + kbh;
        u32 bh[4][4], bl[4][4];
#pragma unroll
        for (int np = 0; np < 4; np++) {
            if (wn * 64 + np * 16 < nv) {
                u32 off = (u32)(wn * 64 + np * 16 + rsel) * RSB + kb;
                ldsm4(bh[np], bh_b + off);
                ldsm4(bl[np], bl_b + off);
            }
        }
#pragma unroll
        for (int mt = 0; mt < 4; mt++) {
            u32 av[4];
            ldsm4(av, a_b + (u32)(wm * 64 + mt * 16 + rsel) * RSB + kb);
#pragma unroll
            for (int nt = 0; nt < 8; nt++) {
                if (wn * 64 + nt * 8 < nv) {
                    u32 b0h = bh[nt >> 1][nt & 1], b1h = bh[nt >> 1][(nt & 1) + 2];
                    u32 b0l = bl[nt >> 1][nt & 1], b1l = bl[nt >> 1][(nt & 1) + 2];
                    mma16816(acc[mt][nt], av, b0h, b1h);
                    mma16816(acc[mt][nt], av, b0l, b1l);
                }
            }
        }
    }
}

// ---------------- table init (fp16 hi/lo, exact integer phase) ---------------
__global__ void k_init() {
    int idx = blockIdx.x * 256 + threadIdx.x;
    if (idx < CUTF * SEQ) {
        int f = idx / SEQ, t = idx - f * SEQ;
        int r = (f * t) % SEQ;
        float s, cc;
        sincospif((float)r * (1.0f / 360.0f), &s, &cc);
        size_t i0 = (size_t)(2 * f) * KD + t;
        size_t i1 = (size_t)(2 * f + 1) * KD + t;
        __half h0 = __float2half_rn(cc);
        d_Eh[i0] = h0; d_El[i0] = __float2half_rn(cc - __half2float(h0));
        __half h1 = __float2half_rn(-s);
        d_Eh[i1] = h1; d_El[i1] = __float2half_rn(-s - __half2float(h1));
    }
    if (idx < SEQ * FOUT) {
        int tp = idx / FOUT, k = idx - tp * FOUT;
        int t = SEQ + tp;
        int m = (k * t) % 1440;
        float s, cc;
        sincospif((float)m * (1.0f / 720.0f), &s, &cc);
        float fc = (k == 0) ? (1.0f / 720.0f) : (cc * (1.0f / 360.0f));
        float fs = (k == 0) ? 0.0f : (-s * (1.0f / 360.0f));
        size_t i0 = (size_t)tp * KO + 2 * k;
        __half h0 = __float2half_rn(fc);
        d_Fh[i0] = h0; d_Fl[i0] = __float2half_rn(fc - __half2float(h0));
        __half h1 = __float2half_rn(fs);
        d_Fh[i0 + 1] = h1; d_Fl[i0 + 1] = __float2half_rn(fs - __half2float(h1));
    }
}

// ---------------- stats ------------------------------------------------------
__global__ void k_stats(const float* __restrict__ x) {
    int c = blockIdx.x * 256 + threadIdx.x;
    int b = blockIdx.y;
    if (c >= CH) return;
    const float* p = x + (size_t)b * SEQ * CH + c;
    float s = 0.f, ss = 0.f;
    for (int t = 0; t < SEQ; t++) {
        float v = p[(size_t)t * CH];
        s += v;
        ss += v * v;
    }
    float mean = s * (1.0f / SEQ);
    float var = (ss - s * mean) * (1.0f / (SEQ - 1));
    float sd = sqrtf(var + 1e-5f);
    d_mean[b * CH + c] = mean;
    d_stdev[b * CH + c] = sd;
    d_invstd[b * CH + c] = 1.0f / sd;
}

// ---------------- transpose in: x[b][t][c] -> xn[c][b][t] fp16 ---------------
__global__ void k_transpose_in(const float* __restrict__ x) {
    __shared__ float sm[32][33];
    int b = blockIdx.z;
    int c0 = blockIdx.x * 32, t0 = blockIdx.y * 32;
    int tx = threadIdx.x, ty = threadIdx.y;
#pragma unroll
    for (int i = 0; i < 4; i++) {
        int t = t0 + ty + i * 8, c = c0 + tx;
        float v = 0.f;
        if (c < CH && t < SEQ)
            v = (x[(size_t)b * SEQ * CH + (size_t)t * CH + c] - d_mean[b * CH + c]) * d_invstd[b * CH + c];
        sm[ty + i * 8][tx] = v;
    }
    __syncthreads();
#pragma unroll
    for (int i = 0; i < 4; i++) {
        int c = c0 + ty + i * 8;
        int t = t0 + tx;
        if (c < CH && t < SEQ)
            d_xn[((size_t)c * BATCH + b) * KD + t] = __float2half_rn(sm[tx][ty + i * 8]);
    }
}

// ---------------- stage 1: DFT GEMM ------------------------------------------
#define NCH1 23
__global__ __launch_bounds__(128, 2) void k_g1() {
    extern __shared__ char smraw[];
    u32 smb = s2u(smraw);
    const int tid = threadIdx.x, lane = tid & 31, warp = tid >> 5;
    const int wm = warp >> 1, wn = warp & 1;
    const int cidx = blockIdx.z, mBase = blockIdx.y * 128, nBase = blockIdx.x * 128;
    const int nv = 400 - nBase > 128 ? 128 : 400 - nBase;
    const char* gA = (const char*)(d_xn + ((size_t)cidx * BATCH + mBase) * KD);
    const char* gBh = (const char*)(d_Eh + (size_t)nBase * KD);
    const char* gBl = (const char*)(d_El + (size_t)nBase * KD);
    float acc[4][8][4] = {};

    cp_tile(smb + 0 * TB, gA, KD * 2, 0, tid);
    cp_tile(smb + 1 * TB, gBh, KD * 2, 0, tid);
    cp_tile(smb + 2 * TB, gBl, KD * 2, 0, tid);
    cp_commit();
    for (int ch = 0; ch < NCH1; ch++) {
        u32 buf = smb + (ch & 1) * 3 * TB;
        if (ch + 1 < NCH1) {
            u32 nb = smb + ((ch + 1) & 1) * 3 * TB;
            int kb = (ch + 1) * 64;
            cp_tile(nb + 0 * TB, gA, KD * 2, kb, tid);
            cp_tile(nb + 1 * TB, gBh, KD * 2, kb, tid);
            cp_tile(nb + 2 * TB, gBl, KD * 2, kb, tid);
            cp_commit();
            cp_wait1();
        } else {
            cp_wait0();
        }
        __syncthreads();
        compute_chunk(acc, buf, buf + TB, buf + 2 * TB, wm, wn, lane, nv);
        __syncthreads();
    }
    const int g = lane >> 2, iq = lane & 3;
#pragma unroll
    for (int mt = 0; mt < 4; mt++) {
        int row = mBase + wm * 64 + mt * 16 + g;
        size_t b0 = ((size_t)cidx * BATCH + row) * KX;
        size_t b1 = b0 + 8 * (size_t)KX;
#pragma unroll
        for (int nt = 0; nt < 8; nt++) {
            int col = nBase + wn * 64 + nt * 8 + 2 * iq;
            if (col < 400) {
                float* cc = acc[mt][nt];
                *(u32*)(d_X + b0 + col) = pack2(cc[0], cc[1]);
                *(u32*)(d_X + b1 + col) = pack2(cc[2], cc[3]);
            }
        }
    }
}

// ---------------- stage 2: complex mixer GEMM --------------------------------
// build W2 chunk (128 o2-rows x 32 k2-cols) hi/lo fp16 into smem; 1 thread = 1 row
__device__ __forceinline__ void build_w2(const float* __restrict__ Wr,
                                         const float* __restrict__ Wi,
                                         int cidx, int nBase, int chunk,
                                         u32 Bh, u32 Bl, int tid) {
    const int o2 = tid;                  // local row 0..127
    const int o = (nBase >> 1) + (o2 >> 1);
    const int p = o2 & 1;
    const u32 base = (u32)o2 * RSB;
    const float* wr = Wr + ((size_t)cidx * FOUT + o) * CUTF;
    const float* wi = Wi + ((size_t)cidx * FOUT + o) * CUTF;
    const bool ov = (o < FOUT);
#pragma unroll
    for (int half = 0; half < 2; half++) {
        int f0 = chunk * 16 + half * 8;
        float wrv[8], wiv[8];
        if (ov && f0 + 8 <= CUTF) {
            float4 a0 = *(const float4*)(wr + f0);
            float4 a1 = *(const float4*)(wr + f0 + 4);
            float4 b0 = *(const float4*)(wi + f0);
            float4 b1 = *(const float4*)(wi + f0 + 4);
            wrv[0] = a0.x; wrv[1] = a0.y; wrv[2] = a0.z; wrv[3] = a0.w;
            wrv[4] = a1.x; wrv[5] = a1.y; wrv[6] = a1.z; wrv[7] = a1.w;
            wiv[0] = b0.x; wiv[1] = b0.y; wiv[2] = b0.z; wiv[3] = b0.w;
            wiv[4] = b1.x; wiv[5] = b1.y; wiv[6] = b1.z; wiv[7] = b1.w;
        } else {
#pragma unroll
            for (int j = 0; j < 8; j++) {
                int f = f0 + j;
                wrv[j] = (ov && f < CUTF) ? wr[f] : 0.f;
                wiv[j] = (ov && f < CUTF) ? wi[f] : 0.f;
            }
        }
#pragma unroll
        for (int q = 0; q < 2; q++) {       // two 16B stores per half
            u32 hh[4], ll[4];
#pragma unroll
            for (int e = 0; e < 4; e++) {
                int j = q * 4 + e;
                float c0 = p ? wiv[j] : wrv[j];
                float c1 = p ? wrv[j] : -wiv[j];
                __half h0 = __float2half_rn(c0), h1 = __float2half_rn(c1);
                hh[e] = (u32)__half_as_ushort(h0) | ((u32)__half_as_ushort(h1) << 16);
                ll[e] = pack2(c0 - __half2float(h0), c1 - __half2float(h1));
            }
            u32 off = base + half * 32 + q * 16;
            asm volatile("st.shared.v4.b32 [%0], {%1,%2,%3,%4};"
                         :: "r"(Bh + off), "r"(hh[0]), "r"(hh[1]), "r"(hh[2]), "r"(hh[3]));
            asm volatile("st.shared.v4.b32 [%0], {%1,%2,%3,%4};"
                         :: "r"(Bl + off), "r"(ll[0]), "r"(ll[1]), "r"(ll[2]), "r"(ll[3]));
        }
    }
}

#define NCH2 13
__global__ __launch_bounds__(128, 2) void k_g2(const float* __restrict__ Wr,
                                               const float* __restrict__ Wi,
                                               const float* __restrict__ br,
                                               const float* __restrict__ bi) {
    extern __shared__ char smraw[];
    u32 smb = s2u(smraw);
    const int tid = threadIdx.x, lane = tid & 31, warp = tid >> 5;
    const int wm = warp >> 1, wn = warp & 1;
    const int cidx = blockIdx.z, mBase = blockIdx.y * 128, nBase = blockIdx.x * 128;
    const int nv = 800 - nBase > 128 ? 128 : 800 - nBase;
    const char* gA = (const char*)(d_X + ((size_t)cidx * BATCH + mBase) * KX);
    float acc[4][8][4] = {};

    cp_tile(smb + 0 * TB, gA, KX * 2, 0, tid);
    cp_commit();
    build_w2(Wr, Wi, cidx, nBase, 0, smb + 1 * TB, smb + 2 * TB, tid);
    for (int ch = 0; ch < NCH2; ch++) {
        u32 buf = smb + (ch & 1) * 3 * TB;
        if (ch + 1 < NCH2) {
            u32 nb = smb + ((ch + 1) & 1) * 3 * TB;
            cp_tile(nb + 0 * TB, gA, KX * 2, (ch + 1) * 64, tid);
            cp_commit();
            build_w2(Wr, Wi, cidx, nBase, ch + 1, nb + 1 * TB, nb + 2 * TB, tid);
            cp_wait1();
        } else {
            cp_wait0();
        }
        __syncthreads();
        compute_chunk(acc, buf, buf + TB, buf + 2 * TB, wm, wn, lane, nv);
        __syncthreads();
    }
    const int g = lane >> 2, iq = lane & 3;
    const float* brp = br + (size_t)cidx * FOUT;
    const float* bip = bi + (size_t)cidx * FOUT;
#pragma unroll
    for (int mt = 0; mt < 4; mt++) {
        int row = mBase + wm * 64 + mt * 16 + g;
        size_t b0 = ((size_t)cidx * BATCH + row) * KO;
        size_t b1 = b0 + 8 * (size_t)KO;
#pragma unroll
        for (int nt = 0; nt < 8; nt++) {
            int col = nBase + wn * 64 + nt * 8 + 2 * iq;
            if (col < 800) {
                int o = col >> 1;
                float vr = brp[o], vi = bip[o];
                float* cc = acc[mt][nt];
                *(u32*)(d_O + b0 + col) = pack2(cc[0] + vr, cc[1] + vi);
                *(u32*)(d_O + b1 + col) = pack2(cc[2] + vr, cc[3] + vi);
            }
        }
    }
}

// ---------------- stage 3: irfft GEMM ----------------------------------------
#define NCH3 25
__global__ __launch_bounds__(128, 2) void k_g3() {
    extern __shared__ char smraw[];
    u32 smb = s2u(smraw);
    const int tid = threadIdx.x, lane = tid & 31, warp = tid >> 5;
    const int wm = warp >> 1, wn = warp & 1;
    const int cidx = blockIdx.z, mBase = blockIdx.y * 128, nBase = blockIdx.x * 128;
    const int nv = 720 - nBase > 128 ? 128 : 720 - nBase;
    const char* gA = (const char*)(d_O + ((size_t)cidx * BATCH + mBase) * KO);
    const char* gBh = (const char*)(d_Fh + (size_t)nBase * KO);
    const char* gBl = (const char*)(d_Fl + (size_t)nBase * KO);
    float acc[4][8][4] = {};

    cp_tile(smb + 0 * TB, gA, KO * 2, 0, tid);
    cp_tile(smb + 1 * TB, gBh, KO * 2, 0, tid);
    cp_tile(smb + 2 * TB, gBl, KO * 2, 0, tid);
    cp_commit();
    for (int ch = 0; ch < NCH3; ch++) {
        u32 buf = smb + (ch & 1) * 3 * TB;
        if (ch + 1 < NCH3) {
            u32 nb = smb + ((ch + 1) & 1) * 3 * TB;
            int kb = (ch + 1) * 64;
            cp_tile(nb + 0 * TB, gA, KO * 2, kb, tid);
            cp_tile(nb + 1 * TB, gBh, KO * 2, kb, tid);
            cp_tile(nb + 2 * TB, gBl, KO * 2, kb, tid);
            cp_commit();
            cp_wait1();
        } else {
            cp_wait0();
        }
        __syncthreads();
        compute_chunk(acc, buf, buf + TB, buf + 2 * TB, wm, wn, lane, nv);
        __syncthreads();
    }
    const int g = lane >> 2, iq = lane & 3;
#pragma unroll
    for (int mt = 0; mt < 4; mt++) {
        int row = mBase + wm * 64 + mt * 16 + g;
        float* y0 = d_y + ((size_t)cidx * BATCH + row) * SEQ;
        float* y1 = y0 + 8 * (size_t)SEQ;
#pragma unroll
        for (int nt = 0; nt < 8; nt++) {
            int col = nBase + wn * 64 + nt * 8 + 2 * iq;
            if (col < SEQ) {
                float* cc = acc[mt][nt];
                *(float2*)(y0 + col) = make_float2(cc[0], cc[1]);
                *(float2*)(y1 + col) = make_float2(cc[2], cc[3]);
            }
        }
    }
}

// ---------------- transpose out: y[c][b][t] -> out[b][t][c], de-norm ---------
__global__ void k_transpose_out(float* __restrict__ out) {
    __shared__ float sm[32][33];
    int b = blockIdx.z;
    int c0 = blockIdx.x * 32, t0 = blockIdx.y * 32;
    int tx = threadIdx.x, ty = threadIdx.y;
#pragma unroll
    for (int i = 0; i < 4; i++) {
        int c = c0 + ty + i * 8;
        int t = t0 + tx;
        float v = 0.f;
        if (c < CH && t < SEQ)
            v = d_y[((size_t)c * BATCH + b) * SEQ + t];
        sm[ty + i * 8][tx] = v;
    }
    __syncthreads();
#pragma unroll
    for (int i = 0; i < 4; i++) {
        int t = t0 + ty + i * 8;
        int c = c0 + tx;
        if (t < SEQ && c < CH) {
            float v = sm[tx][ty + i * 8];
            out[(size_t)b * SEQ * CH + (size_t)t * CH + c] =
                v * d_stdev[b * CH + c] + d_mean[b * CH + c];
        }
    }
}

// ---------------- launch -----------------------------------------------------
extern "C" void kernel_launch(void* const* d_in, const int* in_sizes, int n_in,
                              void* d_out, int out_size) {
    const float* x_enc = (const float*)d_in[0];
    const float* Wr = (const float*)d_in[4];
    const float* Wi = (const float*)d_in[5];
    const float* br = (const float*)d_in[6];
    const float* bi = (const float*)d_in[7];
    float* out = (float*)d_out;

    static int attrDone = 0;
    if (!attrDone) {
        cudaFuncSetAttribute(k_g1, cudaFuncAttributeMaxDynamicSharedMemorySize, SMEM_BYTES);
        cudaFuncSetAttribute(k_g2, cudaFuncAttributeMaxDynamicSharedMemorySize, SMEM_BYTES);
        cudaFuncSetAttribute(k_g3, cudaFuncAttributeMaxDynamicSharedMemorySize, SMEM_BYTES);
        attrDone = 1;
    }

    k_init<<<1125, 256>>>();
    k_stats<<<dim3(2, BATCH), 256>>>(x_enc);
    k_transpose_in<<<dim3(11, 23, BATCH), dim3(32, 8)>>>(x_enc);
    k_g1<<<dim3(4, 2, CH), 128, SMEM_BYTES>>>();
    k_g2<<<dim3(7, 2, CH), 128, SMEM_BYTES>>>(Wr, Wi, br, bi);
    k_g3<<<dim3(6, 2, CH), 128, SMEM_BYTES>>>();
    k_transpose_out<<<dim3(11, 23, BATCH), dim3(32, 8)>>>(out);
}

// round 13
// speedup vs baseline: 1.9582x; 1.9582x over previous
#include <cuda_runtime.h>
#include <cuda_fp16.h>
#include <math.h>
#include <stdint.h>

#define BATCH 256
#define SEQ   720
#define CH    321
#define CUTF  200
#define FOUT  400

#define KD 768    // padded K stage1 (time 720)
#define KX 448    // padded K stage2 (2*CUTF=400)
#define KO 832    // padded K stage3 (2*FOUT=800)
#define N1 512    // padded N stage1
#define N3 768    // padded N stage3

#define RSB 80            // smem row stride bytes (32 fp16 + 16 pad)
#define TB  (128 * RSB)   // one tile: 10240 B
#define SMEM_BYTES (4 * TB)  // 2 stages x 2 tiles = 40960

typedef unsigned int u32;
typedef uint16_t u16;

// ---------------- device scratch ---------------------------------------------
__device__ __align__(256) __half d_E[(size_t)N1 * KD];    // DFT twiddles fp16
__device__ __align__(256) __half d_F[(size_t)N3 * KO];    // irfft twiddles fp16
__device__ __align__(256) __half d_xn[(size_t)CH * BATCH * KD];   // normalized input
__device__ __align__(256) __half d_X[(size_t)CH * BATCH * KX];    // DFT out (interleaved re/im)
__device__ __align__(256) __half d_O[(size_t)CH * BATCH * KO];    // mixer out
__device__ __align__(256) float d_y[(size_t)CH * BATCH * SEQ];
__device__ float d_mean[BATCH * CH];
__device__ float d_stdev[BATCH * CH];
__device__ float d_invstd[BATCH * CH];

// ---------------- helpers ----------------------------------------------------
__device__ __forceinline__ u32 s2u(const void* p) {
    u32 a;
    asm("{ .reg .u64 t; cvta.to.shared.u64 t, %1; cvt.u32.u64 %0, t; }" : "=r"(a) : "l"(p));
    return a;
}
__device__ __forceinline__ void cpa16(u32 dst, const void* src) {
    asm volatile("cp.async.ca.shared.global [%0], [%1], 16;" :: "r"(dst), "l"(src));
}
__device__ __forceinline__ void cp_commit() { asm volatile("cp.async.commit_group;"); }
__device__ __forceinline__ void cp_wait1() { asm volatile("cp.async.wait_group 1;"); }
__device__ __forceinline__ void cp_wait0() { asm volatile("cp.async.wait_group 0;"); }
__device__ __forceinline__ void ldsm4(u32 a[4], u32 addr) {
    asm volatile("ldmatrix.sync.aligned.m8n8.x4.shared.b16 {%0,%1,%2,%3}, [%4];"
                 : "=r"(a[0]), "=r"(a[1]), "=r"(a[2]), "=r"(a[3]) : "r"(addr));
}
__device__ __forceinline__ void mma16816(float c[4], const u32 a[4], u32 b0, u32 b1) {
    asm volatile(
        "mma.sync.aligned.m16n8k16.row.col.f32.f16.f16.f32 "
        "{%0,%1,%2,%3},{%4,%5,%6,%7},{%8,%9},{%0,%1,%2,%3};"
        : "+f"(c[0]), "+f"(c[1]), "+f"(c[2]), "+f"(c[3])
        : "r"(a[0]), "r"(a[1]), "r"(a[2]), "r"(a[3]), "r"(b0), "r"(b1));
}
__device__ __forceinline__ u16 f2h(float v) { return __half_as_ushort(__float2half_rn(v)); }
__device__ __forceinline__ u32 pack2(float a, float b) {
    return (u32)f2h(a) | ((u32)f2h(b) << 16);
}

// cp.async one 128x32fp16 tile (64B/row) into padded smem; 256 threads
__device__ __forceinline__ void cp_tile(u32 smDst, const char* gSrc, int rowStrideBytes,
                                        int kByteOff, int tid) {
    int row = tid >> 1, seg = (tid & 1) * 32;
    const char* s = gSrc + (size_t)row * rowStrideBytes + kByteOff + seg;
    u32 d = smDst + row * RSB + seg;
    cpa16(d, s);
    cpa16(d + 16, s + 16);
}

// one 32-K chunk, single-product fp16; 8 warps (2x4), warp tile 64x32
__device__ __forceinline__ void compute_chunk(float acc[4][4][4], u32 a_b, u32 b_b,
                                              int wm, int wn, int lane, int nv) {
    if (wn * 32 >= nv) return;           // whole warp dead (warp-uniform)
    const int rsel = lane & 15;
    const int kbh = (lane >> 4) * 16;
#pragma unroll
    for (int k16 = 0; k16 < 2; k16++) {
        const int kb = k16 * 32 + kbh;
        u32 bh[2][4];
#pragma unroll
        for (int np = 0; np < 2; np++) {
            if (wn * 32 + np * 16 < nv) {
                u32 off = (u32)(wn * 32 + np * 16 + rsel) * RSB + kb;
                ldsm4(bh[np], b_b + off);
            }
        }
        u32 a[2][4];
        ldsm4(a[0], a_b + (u32)(wm * 64 + rsel) * RSB + kb);
#pragma unroll
        for (int mt = 0; mt < 4; mt++) {
            if (mt < 3)
                ldsm4(a[(mt + 1) & 1], a_b + (u32)(wm * 64 + (mt + 1) * 16 + rsel) * RSB + kb);
            const u32* av = a[mt & 1];
#pragma unroll
            for (int nt = 0; nt < 4; nt++) {
                if (wn * 32 + nt * 8 < nv) {
                    u32 b0 = bh[nt >> 1][nt & 1], b1 = bh[nt >> 1][(nt & 1) + 2];
                    mma16816(acc[mt][nt], av, b0, b1);
                }
            }
        }
    }
}

// ---------------- table init (fp16, exact integer phase) ---------------------
__global__ void k_init() {
    int idx = blockIdx.x * 256 + threadIdx.x;
    if (idx < CUTF * SEQ) {
        int f = idx / SEQ, t = idx - f * SEQ;
        int r = (f * t) % SEQ;
        float s, cc;
        sincospif((float)r * (1.0f / 360.0f), &s, &cc);
        d_E[(size_t)(2 * f) * KD + t] = __float2half_rn(cc);
        d_E[(size_t)(2 * f + 1) * KD + t] = __float2half_rn(-s);
    }
    if (idx < SEQ * FOUT) {
        int tp = idx / FOUT, k = idx - tp * FOUT;
        int t = SEQ + tp;
        int m = (k * t) % 1440;
        float s, cc;
        sincospif((float)m * (1.0f / 720.0f), &s, &cc);
        float fc = (k == 0) ? (1.0f / 720.0f) : (cc * (1.0f / 360.0f));
        float fs = (k == 0) ? 0.0f : (-s * (1.0f / 360.0f));
        size_t i0 = (size_t)tp * KO + 2 * k;
        d_F[i0] = __float2half_rn(fc);
        d_F[i0 + 1] = __float2half_rn(fs);
    }
}

// ---------------- stats ------------------------------------------------------
__global__ void k_stats(const float* __restrict__ x) {
    int c = blockIdx.x * 256 + threadIdx.x;
    int b = blockIdx.y;
    if (c >= CH) return;
    const float* p = x + (size_t)b * SEQ * CH + c;
    float s = 0.f, ss = 0.f;
    for (int t = 0; t < SEQ; t++) {
        float v = p[(size_t)t * CH];
        s += v;
        ss += v * v;
    }
    float mean = s * (1.0f / SEQ);
    float var = (ss - s * mean) * (1.0f / (SEQ - 1));
    float sd = sqrtf(var + 1e-5f);
    d_mean[b * CH + c] = mean;
    d_stdev[b * CH + c] = sd;
    d_invstd[b * CH + c] = 1.0f / sd;
}

// ---------------- transpose in: x[b][t][c] -> xn[c][b][t] fp16 ---------------
__global__ void k_transpose_in(const float* __restrict__ x) {
    __shared__ float sm[32][33];
    int b = blockIdx.z;
    int c0 = blockIdx.x * 32, t0 = blockIdx.y * 32;
    int tx = threadIdx.x, ty = threadIdx.y;
#pragma unroll
    for (int i = 0; i < 4; i++) {
        int t = t0 + ty + i * 8, c = c0 + tx;
        float v = 0.f;
        if (c < CH && t < SEQ)
            v = (x[(size_t)b * SEQ * CH + (size_t)t * CH + c] - d_mean[b * CH + c]) * d_invstd[b * CH + c];
        sm[ty + i * 8][tx] = v;
    }
    __syncthreads();
#pragma unroll
    for (int i = 0; i < 4; i++) {
        int c = c0 + ty + i * 8;
        int t = t0 + tx;
        if (c < CH && t < SEQ)
            d_xn[((size_t)c * BATCH + b) * KD + t] = __float2half_rn(sm[tx][ty + i * 8]);
    }
}

// ---------------- stage 1: DFT GEMM ------------------------------------------
#define NCH1 23
__global__ __launch_bounds__(256, 2) void k_g1() {
    extern __shared__ char smraw[];
    u32 smb = s2u(smraw);
    const int tid = threadIdx.x, lane = tid & 31, warp = tid >> 5;
    const int wm = warp >> 2, wn = warp & 3;
    const int cidx = blockIdx.z, mBase = blockIdx.y * 128, nBase = blockIdx.x * 128;
    const int nv = 400 - nBase > 128 ? 128 : 400 - nBase;
    const char* gA = (const char*)(d_xn + ((size_t)cidx * BATCH + mBase) * KD);
    const char* gB = (const char*)(d_E + (size_t)nBase * KD);
    float acc[4][4][4] = {};

    cp_tile(smb + 0 * TB, gA, KD * 2, 0, tid);
    cp_tile(smb + 1 * TB, gB, KD * 2, 0, tid);
    cp_commit();
    for (int ch = 0; ch < NCH1; ch++) {
        u32 buf = smb + (ch & 1) * 2 * TB;
        if (ch + 1 < NCH1) {
            u32 nb = smb + ((ch + 1) & 1) * 2 * TB;
            int kb = (ch + 1) * 64;
            cp_tile(nb + 0 * TB, gA, KD * 2, kb, tid);
            cp_tile(nb + 1 * TB, gB, KD * 2, kb, tid);
            cp_commit();
            cp_wait1();
        } else {
            cp_wait0();
        }
        __syncthreads();
        compute_chunk(acc, buf, buf + TB, wm, wn, lane, nv);
        __syncthreads();
    }
    const int g = lane >> 2, iq = lane & 3;
#pragma unroll
    for (int mt = 0; mt < 4; mt++) {
        int row = mBase + wm * 64 + mt * 16 + g;
        size_t b0 = ((size_t)cidx * BATCH + row) * KX;
        size_t b1 = b0 + 8 * (size_t)KX;
#pragma unroll
        for (int nt = 0; nt < 4; nt++) {
            int col = nBase + wn * 32 + nt * 8 + 2 * iq;
            if (col < 400) {
                float* cc = acc[mt][nt];
                *(u32*)(d_X + b0 + col) = pack2(cc[0], cc[1]);
                *(u32*)(d_X + b1 + col) = pack2(cc[2], cc[3]);
            }
        }
    }
}

// ---------------- stage 2: complex mixer GEMM --------------------------------
// build W2 chunk (128 o2-rows x 32 k2-cols) fp16 into smem
__device__ __forceinline__ void build_w2(const float* __restrict__ Wr,
                                         const float* __restrict__ Wi,
                                         int cidx, int nBase, int chunk,
                                         u32 Bs, int tid) {
    int oloc = tid >> 1;            // 0..127 local row
    int part = tid & 1;             // 8 f values each
    int o2 = oloc;
    int o = (nBase >> 1) + (o2 >> 1);
    int p = o2 & 1;
    int f0 = chunk * 16 + part * 8;
    float av[8], qv[8];
    const bool ov = (o < FOUT);
    const float* wr = Wr + ((size_t)cidx * FOUT + o) * CUTF;
    const float* wi = Wi + ((size_t)cidx * FOUT + o) * CUTF;
    if (ov && f0 + 8 <= CUTF) {
        float4 a0 = *(const float4*)(wr + f0);
        float4 a1 = *(const float4*)(wr + f0 + 4);
        float4 b0 = *(const float4*)(wi + f0);
        float4 b1 = *(const float4*)(wi + f0 + 4);
        av[0] = a0.x; av[1] = a0.y; av[2] = a0.z; av[3] = a0.w;
        av[4] = a1.x; av[5] = a1.y; av[6] = a1.z; av[7] = a1.w;
        qv[0] = b0.x; qv[1] = b0.y; qv[2] = b0.z; qv[3] = b0.w;
        qv[4] = b1.x; qv[5] = b1.y; qv[6] = b1.z; qv[7] = b1.w;
    } else {
#pragma unroll
        for (int j = 0; j < 8; j++) {
            int f = f0 + j;
            av[j] = (ov && f < CUTF) ? wr[f] : 0.f;
            qv[j] = (ov && f < CUTF) ? wi[f] : 0.f;
        }
    }
    // row even (p=0): (wr, -wi) pairs; row odd (p=1): (wi, wr)
    u32 hh[8];
#pragma unroll
    for (int j = 0; j < 8; j++) {
        float c0 = p ? qv[j] : av[j];
        float c1 = p ? av[j] : -qv[j];
        hh[j] = pack2(c0, c1);
    }
    u32 off = (u32)o2 * RSB + part * 32;
    asm volatile("st.shared.v4.b32 [%0], {%1,%2,%3,%4};"
                 :: "r"(Bs + off), "r"(hh[0]), "r"(hh[1]), "r"(hh[2]), "r"(hh[3]));
    asm volatile("st.shared.v4.b32 [%0], {%1,%2,%3,%4};"
                 :: "r"(Bs + off + 16), "r"(hh[4]), "r"(hh[5]), "r"(hh[6]), "r"(hh[7]));
}

#define NCH2 13
__global__ __launch_bounds__(256, 2) void k_g2(const float* __restrict__ Wr,
                                               const float* __restrict__ Wi,
                                               const float* __restrict__ br,
                                               const float* __restrict__ bi) {
    extern __shared__ char smraw[];
    u32 smb = s2u(smraw);
    const int tid = threadIdx.x, lane = tid & 31, warp = tid >> 5;
    const int wm = warp >> 2, wn = warp & 3;
    const int cidx = blockIdx.z, mBase = blockIdx.y * 128, nBase = blockIdx.x * 128;
    const int nv = 800 - nBase > 128 ? 128 : 800 - nBase;
    const char* gA = (const char*)(d_X + ((size_t)cidx * BATCH + mBase) * KX);
    float acc[4][4][4] = {};

    cp_tile(smb + 0 * TB, gA, KX * 2, 0, tid);
    cp_commit();
    build_w2(Wr, Wi, cidx, nBase, 0, smb + 1 * TB, tid);
    for (int ch = 0; ch < NCH2; ch++) {
        u32 buf = smb + (ch & 1) * 2 * TB;
        if (ch + 1 < NCH2) {
            u32 nb = smb + ((ch + 1) & 1) * 2 * TB;
            cp_tile(nb + 0 * TB, gA, KX * 2, (ch + 1) * 64, tid);
            cp_commit();
            build_w2(Wr, Wi, cidx, nBase, ch + 1, nb + 1 * TB, tid);
            cp_wait1();
        } else {
            cp_wait0();
        }
        __syncthreads();
        compute_chunk(acc, buf, buf + TB, wm, wn, lane, nv);
        __syncthreads();
    }
    const int g = lane >> 2, iq = lane & 3;
    const float* brp = br + (size_t)cidx * FOUT;
    const float* bip = bi + (size_t)cidx * FOUT;
#pragma unroll
    for (int mt = 0; mt < 4; mt++) {
        int row = mBase + wm * 64 + mt * 16 + g;
        size_t b0 = ((size_t)cidx * BATCH + row) * KO;
        size_t b1 = b0 + 8 * (size_t)KO;
#pragma unroll
        for (int nt = 0; nt < 4; nt++) {
            int col = nBase + wn * 32 + nt * 8 + 2 * iq;
            if (col < 800) {
                int o = col >> 1;
                float vr = brp[o], vi = bip[o];
                float* cc = acc[mt][nt];
                *(u32*)(d_O + b0 + col) = pack2(cc[0] + vr, cc[1] + vi);
                *(u32*)(d_O + b1 + col) = pack2(cc[2] + vr, cc[3] + vi);
            }
        }
    }
}

// ---------------- stage 3: irfft GEMM ----------------------------------------
#define NCH3 25
__global__ __launch_bounds__(256, 2) void k_g3() {
    extern __shared__ char smraw[];
    u32 smb = s2u(smraw);
    const int tid = threadIdx.x, lane = tid & 31, warp = tid >> 5;
    const int wm = warp >> 2, wn = warp & 3;
    const int cidx = blockIdx.z, mBase = blockIdx.y * 128, nBase = blockIdx.x * 128;
    const int nv = 720 - nBase > 128 ? 128 : 720 - nBase;
    const char* gA = (const char*)(d_O + ((size_t)cidx * BATCH + mBase) * KO);
    const char* gB = (const char*)(d_F + (size_t)nBase * KO);
    float acc[4][4][4] = {};

    cp_tile(smb + 0 * TB, gA, KO * 2, 0, tid);
    cp_tile(smb + 1 * TB, gB, KO * 2, 0, tid);
    cp_commit();
    for (int ch = 0; ch < NCH3; ch++) {
        u32 buf = smb + (ch & 1) * 2 * TB;
        if (ch + 1 < NCH3) {
            u32 nb = smb + ((ch + 1) & 1) * 2 * TB;
            int kb = (ch + 1) * 64;
            cp_tile(nb + 0 * TB, gA, KO * 2, kb, tid);
            cp_tile(nb + 1 * TB, gB, KO * 2, kb, tid);
            cp_commit();
            cp_wait1();
        } else {
            cp_wait0();
        }
        __syncthreads();
        compute_chunk(acc, buf, buf + TB, wm, wn, lane, nv);
        __syncthreads();
    }
    const int g = lane >> 2, iq = lane & 3;
#pragma unroll
    for (int mt = 0; mt < 4; mt++) {
        int row = mBase + wm * 64 + mt * 16 + g;
        float* y0 = d_y + ((size_t)cidx * BATCH + row) * SEQ;
        float* y1 = y0 + 8 * (size_t)SEQ;
#pragma unroll
        for (int nt = 0; nt < 4; nt++) {
            int col = nBase + wn * 32 + nt * 8 + 2 * iq;
            if (col < SEQ) {
                float* cc = acc[mt][nt];
                *(float2*)(y0 + col) = make_float2(cc[0], cc[1]);
                *(float2*)(y1 + col) = make_float2(cc[2], cc[3]);
            }
        }
    }
}

// ---------------- transpose out: y[c][b][t] -> out[b][t][c], de-norm ---------
__global__ void k_transpose_out(float* __restrict__ out) {
    __shared__ float sm[32][33];
    int b = blockIdx.z;
    int c0 = blockIdx.x * 32, t0 = blockIdx.y * 32;
    int tx = threadIdx.x, ty = threadIdx.y;
#pragma unroll
    for (int i = 0; i < 4; i++) {
        int c = c0 + ty + i * 8;
        int t = t0 + tx;
        float v = 0.f;
        if (c < CH && t < SEQ)
            v = d_y[((size_t)c * BATCH + b) * SEQ + t];
        sm[ty + i * 8][tx] = v;
    }
    __syncthreads();
#pragma unroll
    for (int i = 0; i < 4; i++) {
        int t = t0 + ty + i * 8;
        int c = c0 + tx;
        if (t < SEQ && c < CH) {
            float v = sm[tx][ty + i * 8];
            out[(size_t)b * SEQ * CH + (size_t)t * CH + c] =
                v * d_stdev[b * CH + c] + d_mean[b * CH + c];
        }
    }
}

// ---------------- launch -----------------------------------------------------
extern "C" void kernel_launch(void* const* d_in, const int* in_sizes, int n_in,
                              void* d_out, int out_size) {
    const float* x_enc = (const float*)d_in[0];
    const float* Wr = (const float*)d_in[4];
    const float* Wi = (const float*)d_in[5];
    const float* br = (const float*)d_in[6];
    const float* bi = (const float*)d_in[7];
    float* out = (float*)d_out;

    static int attrDone = 0;
    if (!attrDone) {
        cudaFuncSetAttribute(k_g1, cudaFuncAttributeMaxDynamicSharedMemorySize, SMEM_BYTES);
        cudaFuncSetAttribute(k_g2, cudaFuncAttributeMaxDynamicSharedMemorySize, SMEM_BYTES);
        cudaFuncSetAttribute(k_g3, cudaFuncAttributeMaxDynamicSharedMemorySize, SMEM_BYTES);
        attrDone = 1;
    }

    k_init<<<1125, 256>>>();
    k_stats<<<dim3(2, BATCH), 256>>>(x_enc);
    k_transpose_in<<<dim3(11, 23, BATCH), dim3(32, 8)>>>(x_enc);
    k_g1<<<dim3(4, 2, CH), 256, SMEM_BYTES>>>();
    k_g2<<<dim3(7, 2, CH), 256, SMEM_BYTES>>>(Wr, Wi, br, bi);
    k_g3<<<dim3(6, 2, CH), 256, SMEM_BYTES>>>();
    k_transpose_out<<<dim3(11, 23, BATCH), dim3(32, 8)>>>(out);
}

// round 14
// speedup vs baseline: 1.9844x; 1.0134x over previous
#include <cuda_runtime.h>
#include <cuda_fp16.h>
#include <math.h>
#include <stdint.h>

#define BATCH 256
#define SEQ   720
#define CH    321
#define CUTF  200
#define FOUT  400

#define KD 768    // padded K stage1 (time 720)
#define KX 448    // padded K stage2 (2*CUTF=400)
#define KO 832    // padded K stage3 (2*FOUT=800)
#define N1 512    // padded N stage1
#define N3 768    // padded N stage3

#define RSB 80            // smem row stride bytes (32 fp16 + 16 pad)
#define TB  (128 * RSB)   // one tile: 10240 B
#define SMEM_BYTES (4 * TB)  // 2 stages x 2 tiles = 40960

typedef unsigned int u32;
typedef uint16_t u16;

// ---------------- device scratch ---------------------------------------------
__device__ __align__(256) __half d_E[(size_t)N1 * KD];    // DFT twiddles fp16
__device__ __align__(256) __half d_F[(size_t)N3 * KO];    // irfft twiddles fp16
__device__ __align__(256) __half d_xn[(size_t)CH * BATCH * KD];   // normalized input
__device__ __align__(256) __half d_X[(size_t)CH * BATCH * KX];    // DFT out (interleaved re/im)
__device__ __align__(256) __half d_O[(size_t)CH * BATCH * KO];    // mixer out
__device__ __align__(256) __half d_y[(size_t)CH * BATCH * SEQ];   // irfft out (fp16)
__device__ float d_mean[BATCH * CH];
__device__ float d_stdev[BATCH * CH];
__device__ float d_invstd[BATCH * CH];

// ---------------- helpers ----------------------------------------------------
__device__ __forceinline__ u32 s2u(const void* p) {
    u32 a;
    asm("{ .reg .u64 t; cvta.to.shared.u64 t, %1; cvt.u32.u64 %0, t; }" : "=r"(a) : "l"(p));
    return a;
}
__device__ __forceinline__ void cpa16(u32 dst, const void* src) {
    asm volatile("cp.async.ca.shared.global [%0], [%1], 16;" :: "r"(dst), "l"(src));
}
__device__ __forceinline__ void cp_commit() { asm volatile("cp.async.commit_group;"); }
__device__ __forceinline__ void cp_wait1() { asm volatile("cp.async.wait_group 1;"); }
__device__ __forceinline__ void cp_wait0() { asm volatile("cp.async.wait_group 0;"); }
__device__ __forceinline__ void ldsm4(u32 a[4], u32 addr) {
    asm volatile("ldmatrix.sync.aligned.m8n8.x4.shared.b16 {%0,%1,%2,%3}, [%4];"
                 : "=r"(a[0]), "=r"(a[1]), "=r"(a[2]), "=r"(a[3]) : "r"(addr));
}
__device__ __forceinline__ void mma16816(float c[4], const u32 a[4], u32 b0, u32 b1) {
    asm volatile(
        "mma.sync.aligned.m16n8k16.row.col.f32.f16.f16.f32 "
        "{%0,%1,%2,%3},{%4,%5,%6,%7},{%8,%9},{%0,%1,%2,%3};"
        : "+f"(c[0]), "+f"(c[1]), "+f"(c[2]), "+f"(c[3])
        : "r"(a[0]), "r"(a[1]), "r"(a[2]), "r"(a[3]), "r"(b0), "r"(b1));
}
__device__ __forceinline__ u16 f2h(float v) { return __half_as_ushort(__float2half_rn(v)); }
__device__ __forceinline__ u32 pack2(float a, float b) {
    return (u32)f2h(a) | ((u32)f2h(b) << 16);
}

// cp.async one 128x32fp16 tile (64B/row) into padded smem; 256 threads
__device__ __forceinline__ void cp_tile(u32 smDst, const char* gSrc, int rowStrideBytes,
                                        int kByteOff, int tid) {
    int row = tid >> 1, seg = (tid & 1) * 32;
    const char* s = gSrc + (size_t)row * rowStrideBytes + kByteOff + seg;
    u32 d = smDst + row * RSB + seg;
    cpa16(d, s);
    cpa16(d + 16, s + 16);
}

// one 32-K chunk, single-product fp16; 8 warps (2x4), warp tile 64x32.
// Software-pipelined: B for both k16 groups prefetched, A double-buffered
// across the k16 boundary -> no cold ldsm at group starts.
__device__ __forceinline__ void compute_chunk(float acc[4][4][4], u32 a_b, u32 b_b,
                                              int wm, int wn, int lane, int nv) {
    if (wn * 32 >= nv) return;           // whole warp dead (warp-uniform)
    const int rsel = lane & 15;
    const int kbh = (lane >> 4) * 16;
    const u32 aBase = a_b + (u32)(wm * 64 + rsel) * RSB + kbh;
    const u32 bBase = b_b + (u32)(wn * 32 + rsel) * RSB + kbh;
    const bool nv1 = (wn * 32 + 16) < nv;

    u32 b0[2][4], b1[2][4];
    ldsm4(b0[0], bBase);                        // k16=0, np=0
    if (nv1) ldsm4(b0[1], bBase + 16 * RSB);    // k16=0, np=1
    u32 a[2][4];
    ldsm4(a[0], aBase);                         // mt=0, k16=0

    // k16 = 0
#pragma unroll
    for (int mt = 0; mt < 4; mt++) {
        if (mt < 3) ldsm4(a[(mt + 1) & 1], aBase + (u32)(mt + 1) * 16 * RSB);
        else        ldsm4(a[(mt + 1) & 1], aBase + 32);              // mt=0 of k16=1
        if (mt == 1) {
            ldsm4(b1[0], bBase + 32);                                 // k16=1 B prefetch
            if (nv1) ldsm4(b1[1], bBase + 16 * RSB + 32);
        }
        const u32* av = a[mt & 1];
#pragma unroll
        for (int nt = 0; nt < 4; nt++) {
            if (wn * 32 + nt * 8 < nv)
                mma16816(acc[mt][nt], av, b0[nt >> 1][nt & 1], b0[nt >> 1][(nt & 1) + 2]);
        }
    }
    // k16 = 1
#pragma unroll
    for (int mt = 0; mt < 4; mt++) {
        if (mt < 3) ldsm4(a[(mt + 1) & 1], aBase + (u32)(mt + 1) * 16 * RSB + 32);
        const u32* av = a[mt & 1];
#pragma unroll
        for (int nt = 0; nt < 4; nt++) {
            if (wn * 32 + nt * 8 < nv)
                mma16816(acc[mt][nt], av, b1[nt >> 1][nt & 1], b1[nt >> 1][(nt & 1) + 2]);
        }
    }
}

// ---------------- table init (fp16, exact integer phase) ---------------------
__global__ void k_init() {
    int idx = blockIdx.x * 256 + threadIdx.x;
    if (idx < CUTF * SEQ) {
        int f = idx / SEQ, t = idx - f * SEQ;
        int r = (f * t) % SEQ;
        float s, cc;
        sincospif((float)r * (1.0f / 360.0f), &s, &cc);
        d_E[(size_t)(2 * f) * KD + t] = __float2half_rn(cc);
        d_E[(size_t)(2 * f + 1) * KD + t] = __float2half_rn(-s);
    }
    if (idx < SEQ * FOUT) {
        int tp = idx / FOUT, k = idx - tp * FOUT;
        int t = SEQ + tp;
        int m = (k * t) % 1440;
        float s, cc;
        sincospif((float)m * (1.0f / 720.0f), &s, &cc);
        float fc = (k == 0) ? (1.0f / 720.0f) : (cc * (1.0f / 360.0f));
        float fs = (k == 0) ? 0.0f : (-s * (1.0f / 360.0f));
        size_t i0 = (size_t)tp * KO + 2 * k;
        d_F[i0] = __float2half_rn(fc);
        d_F[i0 + 1] = __float2half_rn(fs);
    }
}

// ---------------- stats ------------------------------------------------------
__global__ void k_stats(const float* __restrict__ x) {
    int c = blockIdx.x * 256 + threadIdx.x;
    int b = blockIdx.y;
    if (c >= CH) return;
    const float* p = x + (size_t)b * SEQ * CH + c;
    float s = 0.f, ss = 0.f;
    for (int t = 0; t < SEQ; t++) {
        float v = p[(size_t)t * CH];
        s += v;
        ss += v * v;
    }
    float mean = s * (1.0f / SEQ);
    float var = (ss - s * mean) * (1.0f / (SEQ - 1));
    float sd = sqrtf(var + 1e-5f);
    d_mean[b * CH + c] = mean;
    d_stdev[b * CH + c] = sd;
    d_invstd[b * CH + c] = 1.0f / sd;
}

// ---------------- transpose in: x[b][t][c] -> xn[c][b][t] fp16 ---------------
__global__ void k_transpose_in(const float* __restrict__ x) {
    __shared__ float sm[32][33];
    int b = blockIdx.z;
    int c0 = blockIdx.x * 32, t0 = blockIdx.y * 32;
    int tx = threadIdx.x, ty = threadIdx.y;
#pragma unroll
    for (int i = 0; i < 4; i++) {
        int t = t0 + ty + i * 8, c = c0 + tx;
        float v = 0.f;
        if (c < CH && t < SEQ)
            v = (x[(size_t)b * SEQ * CH + (size_t)t * CH + c] - d_mean[b * CH + c]) * d_invstd[b * CH + c];
        sm[ty + i * 8][tx] = v;
    }
    __syncthreads();
#pragma unroll
    for (int i = 0; i < 4; i++) {
        int c = c0 + ty + i * 8;
        int t = t0 + tx;
        if (c < CH && t < SEQ)
            d_xn[((size_t)c * BATCH + b) * KD + t] = __float2half_rn(sm[tx][ty + i * 8]);
    }
}

// ---------------- stage 1: DFT GEMM ------------------------------------------
#define NCH1 23
__global__ __launch_bounds__(256, 2) void k_g1() {
    extern __shared__ char smraw[];
    u32 smb = s2u(smraw);
    const int tid = threadIdx.x, lane = tid & 31, warp = tid >> 5;
    const int wm = warp >> 2, wn = warp & 3;
    const int cidx = blockIdx.z, mBase = blockIdx.y * 128, nBase = blockIdx.x * 128;
    const int nv = 400 - nBase > 128 ? 128 : 400 - nBase;
    const char* gA = (const char*)(d_xn + ((size_t)cidx * BATCH + mBase) * KD);
    const char* gB = (const char*)(d_E + (size_t)nBase * KD);
    float acc[4][4][4] = {};

    cp_tile(smb + 0 * TB, gA, KD * 2, 0, tid);
    cp_tile(smb + 1 * TB, gB, KD * 2, 0, tid);
    cp_commit();
    for (int ch = 0; ch < NCH1; ch++) {
        u32 buf = smb + (ch & 1) * 2 * TB;
        if (ch + 1 < NCH1) {
            u32 nb = smb + ((ch + 1) & 1) * 2 * TB;
            int kb = (ch + 1) * 64;
            cp_tile(nb + 0 * TB, gA, KD * 2, kb, tid);
            cp_tile(nb + 1 * TB, gB, KD * 2, kb, tid);
            cp_commit();
            cp_wait1();
        } else {
            cp_wait0();
        }
        __syncthreads();
        compute_chunk(acc, buf, buf + TB, wm, wn, lane, nv);
        __syncthreads();
    }
    const int g = lane >> 2, iq = lane & 3;
#pragma unroll
    for (int mt = 0; mt < 4; mt++) {
        int row = mBase + wm * 64 + mt * 16 + g;
        size_t b0 = ((size_t)cidx * BATCH + row) * KX;
        size_t b1 = b0 + 8 * (size_t)KX;
#pragma unroll
        for (int nt = 0; nt < 4; nt++) {
            int col = nBase + wn * 32 + nt * 8 + 2 * iq;
            if (col < 400) {
                float* cc = acc[mt][nt];
                *(u32*)(d_X + b0 + col) = pack2(cc[0], cc[1]);
                *(u32*)(d_X + b1 + col) = pack2(cc[2], cc[3]);
            }
        }
    }
}

// ---------------- stage 2: complex mixer GEMM --------------------------------
// build W2 chunk (128 o2-rows x 32 k2-cols) fp16 into smem
__device__ __forceinline__ void build_w2(const float* __restrict__ Wr,
                                         const float* __restrict__ Wi,
                                         int cidx, int nBase, int chunk,
                                         u32 Bs, int tid) {
    int oloc = tid >> 1;            // 0..127 local row
    int part = tid & 1;             // 8 f values each
    int o2 = oloc;
    int o = (nBase >> 1) + (o2 >> 1);
    int p = o2 & 1;
    int f0 = chunk * 16 + part * 8;
    float av[8], qv[8];
    const bool ov = (o < FOUT);
    const float* wr = Wr + ((size_t)cidx * FOUT + o) * CUTF;
    const float* wi = Wi + ((size_t)cidx * FOUT + o) * CUTF;
    if (ov && f0 + 8 <= CUTF) {
        float4 a0 = *(const float4*)(wr + f0);
        float4 a1 = *(const float4*)(wr + f0 + 4);
        float4 b0 = *(const float4*)(wi + f0);
        float4 b1 = *(const float4*)(wi + f0 + 4);
        av[0] = a0.x; av[1] = a0.y; av[2] = a0.z; av[3] = a0.w;
        av[4] = a1.x; av[5] = a1.y; av[6] = a1.z; av[7] = a1.w;
        qv[0] = b0.x; qv[1] = b0.y; qv[2] = b0.z; qv[3] = b0.w;
        qv[4] = b1.x; qv[5] = b1.y; qv[6] = b1.z; qv[7] = b1.w;
    } else {
#pragma unroll
        for (int j = 0; j < 8; j++) {
            int f = f0 + j;
            av[j] = (ov && f < CUTF) ? wr[f] : 0.f;
            qv[j] = (ov && f < CUTF) ? wi[f] : 0.f;
        }
    }
    // row even (p=0): (wr, -wi) pairs; row odd (p=1): (wi, wr)
    u32 hh[8];
#pragma unroll
    for (int j = 0; j < 8; j++) {
        float c0 = p ? qv[j] : av[j];
        float c1 = p ? av[j] : -qv[j];
        hh[j] = pack2(c0, c1);
    }
    u32 off = (u32)o2 * RSB + part * 32;
    asm volatile("st.shared.v4.b32 [%0], {%1,%2,%3,%4};"
                 :: "r"(Bs + off), "r"(hh[0]), "r"(hh[1]), "r"(hh[2]), "r"(hh[3]));
    asm volatile("st.shared.v4.b32 [%0], {%1,%2,%3,%4};"
                 :: "r"(Bs + off + 16), "r"(hh[4]), "r"(hh[5]), "r"(hh[6]), "r"(hh[7]));
}

#define NCH2 13
__global__ __launch_bounds__(256, 2) void k_g2(const float* __restrict__ Wr,
                                               const float* __restrict__ Wi,
                                               const float* __restrict__ br,
                                               const float* __restrict__ bi) {
    extern __shared__ char smraw[];
    u32 smb = s2u(smraw);
    const int tid = threadIdx.x, lane = tid & 31, warp = tid >> 5;
    const int wm = warp >> 2, wn = warp & 3;
    const int cidx = blockIdx.z, mBase = blockIdx.y * 128, nBase = blockIdx.x * 128;
    const int nv = 800 - nBase > 128 ? 128 : 800 - nBase;
    const char* gA = (const char*)(d_X + ((size_t)cidx * BATCH + mBase) * KX);
    float acc[4][4][4] = {};

    cp_tile(smb + 0 * TB, gA, KX * 2, 0, tid);
    cp_commit();
    build_w2(Wr, Wi, cidx, nBase, 0, smb + 1 * TB, tid);
    for (int ch = 0; ch < NCH2; ch++) {
        u32 buf = smb + (ch & 1) * 2 * TB;
        if (ch + 1 < NCH2) {
            u32 nb = smb + ((ch + 1) & 1) * 2 * TB;
            cp_tile(nb + 0 * TB, gA, KX * 2, (ch + 1) * 64, tid);
            cp_commit();
            build_w2(Wr, Wi, cidx, nBase, ch + 1, nb + 1 * TB, tid);
            cp_wait1();
        } else {
            cp_wait0();
        }
        __syncthreads();
        compute_chunk(acc, buf, buf + TB, wm, wn, lane, nv);
        __syncthreads();
    }
    const int g = lane >> 2, iq = lane & 3;
    const float* brp = br + (size_t)cidx * FOUT;
    const float* bip = bi + (size_t)cidx * FOUT;
#pragma unroll
    for (int mt = 0; mt < 4; mt++) {
        int row = mBase + wm * 64 + mt * 16 + g;
        size_t b0 = ((size_t)cidx * BATCH + row) * KO;
        size_t b1 = b0 + 8 * (size_t)KO;
#pragma unroll
        for (int nt = 0; nt < 4; nt++) {
            int col = nBase + wn * 32 + nt * 8 + 2 * iq;
            if (col < 800) {
                int o = col >> 1;
                float vr = brp[o], vi = bip[o];
                float* cc = acc[mt][nt];
                *(u32*)(d_O + b0 + col) = pack2(cc[0] + vr, cc[1] + vi);
                *(u32*)(d_O + b1 + col) = pack2(cc[2] + vr, cc[3] + vi);
            }
        }
    }
}

// ---------------- stage 3: irfft GEMM ----------------------------------------
#define NCH3 25
__global__ __launch_bounds__(256, 2) void k_g3() {
    extern __shared__ char smraw[];
    u32 smb = s2u(smraw);
    const int tid = threadIdx.x, lane = tid & 31, warp = tid >> 5;
    const int wm = warp >> 2, wn = warp & 3;
    const int cidx = blockIdx.z, mBase = blockIdx.y * 128, nBase = blockIdx.x * 128;
    const int nv = 720 - nBase > 128 ? 128 : 720 - nBase;
    const char* gA = (const char*)(d_O + ((size_t)cidx * BATCH + mBase) * KO);
    const char* gB = (const char*)(d_F + (size_t)nBase * KO);
    float acc[4][4][4] = {};

    cp_tile(smb + 0 * TB, gA, KO * 2, 0, tid);
    cp_tile(smb + 1 * TB, gB, KO * 2, 0, tid);
    cp_commit();
    for (int ch = 0; ch < NCH3; ch++) {
        u32 buf = smb + (ch & 1) * 2 * TB;
        if (ch + 1 < NCH3) {
            u32 nb = smb + ((ch + 1) & 1) * 2 * TB;
            int kb = (ch + 1) * 64;
            cp_tile(nb + 0 * TB, gA, KO * 2, kb, tid);
            cp_tile(nb + 1 * TB, gB, KO * 2, kb, tid);
            cp_commit();
            cp_wait1();
        } else {
            cp_wait0();
        }
        __syncthreads();
        compute_chunk(acc, buf, buf + TB, wm, wn, lane, nv);
        __syncthreads();
    }
    const int g = lane >> 2, iq = lane & 3;
#pragma unroll
    for (int mt = 0; mt < 4; mt++) {
        int row = mBase + wm * 64 + mt * 16 + g;
        __half* y0 = d_y + ((size_t)cidx * BATCH + row) * SEQ;
        __half* y1 = y0 + 8 * (size_t)SEQ;
#pragma unroll
        for (int nt = 0; nt < 4; nt++) {
            int col = nBase + wn * 32 + nt * 8 + 2 * iq;
            if (col < SEQ) {
                float* cc = acc[mt][nt];
                *(u32*)(y0 + col) = pack2(cc[0], cc[1]);
                *(u32*)(y1 + col) = pack2(cc[2], cc[3]);
            }
        }
    }
}

// ---------------- transpose out: y[c][b][t] -> out[b][t][c], de-norm ---------
__global__ void k_transpose_out(float* __restrict__ out) {
    __shared__ float sm[32][33];
    int b = blockIdx.z;
    int c0 = blockIdx.x * 32, t0 = blockIdx.y * 32;
    int tx = threadIdx.x, ty = threadIdx.y;
#pragma unroll
    for (int i = 0; i < 4; i++) {
        int c = c0 + ty + i * 8;
        int t = t0 + tx;
        float v = 0.f;
        if (c < CH && t < SEQ)
            v = __half2float(d_y[((size_t)c * BATCH + b) * SEQ + t]);
        sm[ty + i * 8][tx] = v;
    }
    __syncthreads();
#pragma unroll
    for (int i = 0; i < 4; i++) {
        int t = t0 + ty + i * 8;
        int c = c0 + tx;
        if (t < SEQ && c < CH) {
            float v = sm[tx][ty + i * 8];
            out[(size_t)b * SEQ * CH + (size_t)t * CH + c] =
                v * d_stdev[b * CH + c] + d_mean[b * CH + c];
        }
    }
}

// ---------------- launch -----------------------------------------------------
extern "C" void kernel_launch(void* const* d_in, const int* in_sizes, int n_in,
                              void* d_out, int out_size) {
    const float* x_enc = (const float*)d_in[0];
    const float* Wr = (const float*)d_in[4];
    const float* Wi = (const float*)d_in[5];
    const float* br = (const float*)d_in[6];
    const float* bi = (const float*)d_in[7];
    float* out = (float*)d_out;

    static int attrDone = 0;
    if (!attrDone) {
        cudaFuncSetAttribute(k_g1, cudaFuncAttributeMaxDynamicSharedMemorySize, SMEM_BYTES);
        cudaFuncSetAttribute(k_g2, cudaFuncAttributeMaxDynamicSharedMemorySize, SMEM_BYTES);
        cudaFuncSetAttribute(k_g3, cudaFuncAttributeMaxDynamicSharedMemorySize, SMEM_BYTES);
        attrDone = 1;
    }

    k_init<<<1125, 256>>>();
    k_stats<<<dim3(2, BATCH), 256>>>(x_enc);
    k_transpose_in<<<dim3(11, 23, BATCH), dim3(32, 8)>>>(x_enc);
    k_g1<<<dim3(4, 2, CH), 256, SMEM_BYTES>>>();
    k_g2<<<dim3(7, 2, CH), 256, SMEM_BYTES>>>(Wr, Wi, br, bi);
    k_g3<<<dim3(6, 2, CH), 256, SMEM_BYTES>>>();
    k_transpose_out<<<dim3(11, 23, BATCH), dim3(32, 8)>>>(out);
}

// round 15
// speedup vs baseline: 1.9920x; 1.0038x over previous
#include <cuda_runtime.h>
#include <cuda_fp16.h>
#include <math.h>
#include <stdint.h>

#define BATCH 256
#define SEQ   720
#define CH    321
#define CUTF  200
#define FOUT  400

#define KU  384   // padded half-length K (361 -> 384) for stage 1
#define KX  448   // stage2 K: [Re 224 | Im 224]
#define KS  448   // stage3 K per half (400 -> 448)
#define NU  384   // stage3 N (u: 361 -> 384)

#define RSB 80            // smem row stride bytes (32 fp16 + 16 pad)
#define TB  (128 * RSB)   // one tile: 10240 B
#define SMEM_BYTES (4 * TB)

typedef unsigned int u32;
typedef uint16_t u16;

// ---------------- device scratch ---------------------------------------------
__device__ __align__(256) __half d_E1[(size_t)512 * KU];         // [cos f<256 | -sin]
__device__ __align__(256) __half d_G[(size_t)2 * NU * KS];       // Gs, Gd
__device__ __align__(256) __half d_xe[(size_t)CH * BATCH * (2 * KU)];  // [xe 384 | xo 384]
__device__ __align__(256) __half d_X[(size_t)CH * BATCH * KX];   // [Re 224 | Im 224]
__device__ __align__(256) __half d_OS[(size_t)CH * BATCH * KS];  // S-group columns
__device__ __align__(256) __half d_OD[(size_t)CH * BATCH * KS];  // D-group columns
__device__ __align__(256) __half d_S[(size_t)CH * BATCH * NU];
__device__ __align__(256) __half d_D[(size_t)CH * BATCH * NU];
__device__ float d_mean[BATCH * CH];
__device__ float d_stdev[BATCH * CH];
__device__ float d_invstd[BATCH * CH];

// ---------------- helpers ----------------------------------------------------
__device__ __forceinline__ u32 s2u(const void* p) {
    u32 a;
    asm("{ .reg .u64 t; cvta.to.shared.u64 t, %1; cvt.u32.u64 %0, t; }" : "=r"(a) : "l"(p));
    return a;
}
__device__ __forceinline__ void cpa16(u32 dst, const void* src) {
    asm volatile("cp.async.ca.shared.global [%0], [%1], 16;" :: "r"(dst), "l"(src));
}
__device__ __forceinline__ void cp_commit() { asm volatile("cp.async.commit_group;"); }
__device__ __forceinline__ void cp_wait1() { asm volatile("cp.async.wait_group 1;"); }
__device__ __forceinline__ void cp_wait0() { asm volatile("cp.async.wait_group 0;"); }
__device__ __forceinline__ void ldsm4(u32 a[4], u32 addr) {
    asm volatile("ldmatrix.sync.aligned.m8n8.x4.shared.b16 {%0,%1,%2,%3}, [%4];"
                 : "=r"(a[0]), "=r"(a[1]), "=r"(a[2]), "=r"(a[3]) : "r"(addr));
}
__device__ __forceinline__ void mma16816(float c[4], const u32 a[4], u32 b0, u32 b1) {
    asm volatile(
        "mma.sync.aligned.m16n8k16.row.col.f32.f16.f16.f32 "
        "{%0,%1,%2,%3},{%4,%5,%6,%7},{%8,%9},{%0,%1,%2,%3};"
        : "+f"(c[0]), "+f"(c[1]), "+f"(c[2]), "+f"(c[3])
        : "r"(a[0]), "r"(a[1]), "r"(a[2]), "r"(a[3]), "r"(b0), "r"(b1));
}
__device__ __forceinline__ u16 f2h(float v) { return __half_as_ushort(__float2half_rn(v)); }
__device__ __forceinline__ u32 pack2(float a, float b) {
    return (u32)f2h(a) | ((u32)f2h(b) << 16);
}

// cp.async one 128x32fp16 tile (64B/row) into padded smem; 256 threads
__device__ __forceinline__ void cp_tile(u32 smDst, const char* gSrc, int rowStrideBytes,
                                        int kByteOff, int tid) {
    int row = tid >> 1, seg = (tid & 1) * 32;
    const char* s = gSrc + (size_t)row * rowStrideBytes + kByteOff + seg;
    u32 d = smDst + row * RSB + seg;
    cpa16(d, s);
    cpa16(d + 16, s + 16);
}

// one 32-K chunk, single-product fp16; 8 warps (2x4), warp tile 64x32.
__device__ __forceinline__ void compute_chunk(float acc[4][4][4], u32 a_b, u32 b_b,
                                              int wm, int wn, int lane, int nv) {
    if (wn * 32 >= nv) return;
    const int rsel = lane & 15;
    const int kbh = (lane >> 4) * 16;
    const u32 aBase = a_b + (u32)(wm * 64 + rsel) * RSB + kbh;
    const u32 bBase = b_b + (u32)(wn * 32 + rsel) * RSB + kbh;
    const bool nv1 = (wn * 32 + 16) < nv;

    u32 b0[2][4], b1[2][4];
    ldsm4(b0[0], bBase);
    if (nv1) ldsm4(b0[1], bBase + 16 * RSB);
    u32 a[2][4];
    ldsm4(a[0], aBase);

#pragma unroll
    for (int mt = 0; mt < 4; mt++) {
        if (mt < 3) ldsm4(a[(mt + 1) & 1], aBase + (u32)(mt + 1) * 16 * RSB);
        else        ldsm4(a[(mt + 1) & 1], aBase + 32);
        if (mt == 1) {
            ldsm4(b1[0], bBase + 32);
            if (nv1) ldsm4(b1[1], bBase + 16 * RSB + 32);
        }
        const u32* av = a[mt & 1];
#pragma unroll
        for (int nt = 0; nt < 4; nt++) {
            if (wn * 32 + nt * 8 < nv)
                mma16816(acc[mt][nt], av, b0[nt >> 1][nt & 1], b0[nt >> 1][(nt & 1) + 2]);
        }
    }
#pragma unroll
    for (int mt = 0; mt < 4; mt++) {
        if (mt < 3) ldsm4(a[(mt + 1) & 1], aBase + (u32)(mt + 1) * 16 * RSB + 32);
        const u32* av = a[mt & 1];
#pragma unroll
        for (int nt = 0; nt < 4; nt++) {
            if (wn * 32 + nt * 8 < nv)
                mma16816(acc[mt][nt], av, b1[nt >> 1][nt & 1], b1[nt >> 1][(nt & 1) + 2]);
        }
    }
}

// ---------------- table init -------------------------------------------------
// E1: rows [0,256): cos(2*pi*f*u/720), f=row (valid f<200, u<=360)
//     rows [256,512): -sin(2*pi*f*u/720), f=row-256
// G[0]=Gs[u][k]: k<400,u<=360: k even ? sc*cos(2*pi*k*u/1440) : -sc*sin(...)
// G[1]=Gd[u][k]: k even ? -sc*sin : sc*cos ; sc = (k==0 ? 1/720 : 1/360)
__global__ void k_init() {
    int idx = blockIdx.x * 256 + threadIdx.x;
    if (idx < 512 * KU) {
        int r = idx / KU, u = idx - r * KU;
        int f = r & 255;
        float v = 0.f;
        if (f < CUTF && u <= 360) {
            int m = (f * u) % 720;
            float s, c;
            sincospif((float)m * (1.0f / 360.0f), &s, &c);
            v = (r < 256) ? c : -s;
        }
        d_E1[idx] = __float2half_rn(v);
    }
    if (idx < 2 * NU * KS) {
        int which = idx / (NU * KS);
        int rem = idx - which * (NU * KS);
        int u = rem / KS, k = rem - u * KS;
        float v = 0.f;
        if (k < 2 * CUTF && u <= 360) {
            int m = (k * u) % 1440;
            float s, c;
            sincospif((float)m * (1.0f / 720.0f), &s, &c);
            float sc = (k == 0) ? (1.0f / 720.0f) : (1.0f / 360.0f);
            bool ke = (k & 1) == 0;
            if (which == 0) v = ke ? sc * c : -sc * s;   // Gs
            else            v = ke ? -sc * s : sc * c;   // Gd
        }
        d_G[idx] = __float2half_rn(v);
    }
}

// ---------------- stats ------------------------------------------------------
__global__ void k_stats(const float* __restrict__ x) {
    int c = blockIdx.x * 256 + threadIdx.x;
    int b = blockIdx.y;
    if (c >= CH) return;
    const float* p = x + (size_t)b * SEQ * CH + c;
    float s = 0.f, ss = 0.f;
    for (int t = 0; t < SEQ; t++) {
        float v = p[(size_t)t * CH];
        s += v;
        ss += v * v;
    }
    float mean = s * (1.0f / SEQ);
    float var = (ss - s * mean) * (1.0f / (SEQ - 1));
    float sd = sqrtf(var + 1e-5f);
    d_mean[b * CH + c] = mean;
    d_stdev[b * CH + c] = sd;
    d_invstd[b * CH + c] = 1.0f / sd;
}

// ---------------- prep: x[b][t][c] -> xe/xo [c][b][u] fp16 -------------------
__global__ void k_prep(const float* __restrict__ x) {
    __shared__ float sa[32][33];   // xn[u]
    __shared__ float sb[32][33];   // xn[720-u]
    int b = blockIdx.z;
    int c0 = blockIdx.x * 32, u0 = blockIdx.y * 32;
    int tx = threadIdx.x, ty = threadIdx.y;
#pragma unroll
    for (int i = 0; i < 4; i++) {
        int u = u0 + ty + i * 8, c = c0 + tx;
        float va = 0.f, vb = 0.f;
        if (c < CH) {
            float mean = d_mean[b * CH + c], inv = d_invstd[b * CH + c];
            if (u < SEQ)
                va = (x[(size_t)b * SEQ * CH + (size_t)u * CH + c] - mean) * inv;
            int tb = 720 - u;
            if (u >= 1 && u <= 359)
                vb = (x[(size_t)b * SEQ * CH + (size_t)tb * CH + c] - mean) * inv;
        }
        sa[ty + i * 8][tx] = va;
        sb[ty + i * 8][tx] = vb;
    }
    __syncthreads();
#pragma unroll
    for (int i = 0; i < 4; i++) {
        int c = c0 + ty + i * 8;
        int u = u0 + tx;
        if (c < CH && u <= 360) {
            float xnu = sa[tx][ty + i * 8];
            float pa = sb[tx][ty + i * 8];       // 0 unless 1<=u<=359
            bool pv = (u >= 1 && u <= 359);
            float xe = xnu + pa;
            float xo = pv ? (xnu - pa) : 0.f;
            size_t base = ((size_t)c * BATCH + b) * (2 * KU);
            d_xe[base + u] = __float2half_rn(xe);
            d_xe[base + KU + u] = __float2half_rn(xo);
        }
    }
}

// ---------------- stage 1: DFT (two half-GEMMs: Re over xe, Im over xo) ------
#define NCH1 12
__global__ __launch_bounds__(256, 2) void k_g1() {
    extern __shared__ char smraw[];
    u32 smb = s2u(smraw);
    const int tid = threadIdx.x, lane = tid & 31, warp = tid >> 5;
    const int wm = warp >> 2, wn = warp & 3;
    const int cidx = blockIdx.z, mBase = blockIdx.y * 128;
    const int half = blockIdx.x >> 1;           // 0=Re, 1=Im
    const int nBase = (blockIdx.x & 1) * 128;   // f block
    const int nv = CUTF - nBase > 128 ? 128 : CUTF - nBase;
    const char* gA = (const char*)(d_xe + ((size_t)cidx * BATCH + mBase) * (2 * KU) + half * KU);
    const char* gB = (const char*)(d_E1 + (size_t)(half * 256 + nBase) * KU);
    float acc[4][4][4] = {};

    cp_tile(smb + 0 * TB, gA, 2 * KU * 2, 0, tid);
    cp_tile(smb + 1 * TB, gB, KU * 2, 0, tid);
    cp_commit();
    for (int ch = 0; ch < NCH1; ch++) {
        u32 buf = smb + (ch & 1) * 2 * TB;
        if (ch + 1 < NCH1) {
            u32 nb = smb + ((ch + 1) & 1) * 2 * TB;
            int kb = (ch + 1) * 64;
            cp_tile(nb + 0 * TB, gA, 2 * KU * 2, kb, tid);
            cp_tile(nb + 1 * TB, gB, KU * 2, kb, tid);
            cp_commit();
            cp_wait1();
        } else {
            cp_wait0();
        }
        __syncthreads();
        compute_chunk(acc, buf, buf + TB, wm, wn, lane, nv);
        __syncthreads();
    }
    const int g = lane >> 2, iq = lane & 3;
    const int regionOff = half * 224;
#pragma unroll
    for (int mt = 0; mt < 4; mt++) {
        int row = mBase + wm * 64 + mt * 16 + g;
        size_t b0 = ((size_t)cidx * BATCH + row) * KX + regionOff;
        size_t b1 = b0 + 8 * (size_t)KX;
#pragma unroll
        for (int nt = 0; nt < 4; nt++) {
            int f = nBase + wn * 32 + nt * 8 + 2 * iq;
            if (f < CUTF) {
                float* cc = acc[mt][nt];
                *(u32*)(d_X + b0 + f) = pack2(cc[0], cc[1]);
                *(u32*)(d_X + b1 + f) = pack2(cc[2], cc[3]);
            }
        }
    }
}

// ---------------- stage 2: complex mixer -------------------------------------
// B[o2][k2]: k2<224 (Re region, f=k2):  o2 even -> wr[o][f], odd -> wi[o][f]
//            k2>=224 (Im region, f=k2-224): o2 even -> -wi[o][f], odd -> wr[o][f]
__device__ __forceinline__ void build_w2(const float* __restrict__ Wr,
                                         const float* __restrict__ Wi,
                                         int cidx, int nBase, int ch,
                                         u32 Bs, int tid) {
    int o2 = tid >> 1;
    int part = tid & 1;
    int o = (nBase >> 1) + (o2 >> 1);
    int p = o2 & 1;
    int k20 = ch * 32 + part * 16;
    bool reg = (ch < 7);                 // chunk 7 starts exactly at k2=224
    int f0 = k20 - (reg ? 0 : 224);
    const bool ov = (o < FOUT);
    const float* wsrc;
    float sgn;
    if (reg) { wsrc = p ? Wi : Wr; sgn = 1.f; }
    else     { wsrc = p ? Wr : Wi; sgn = p ? 1.f : -1.f; }
    const float* w = wsrc + ((size_t)cidx * FOUT + o) * CUTF;

    float v[16];
    if (ov && f0 + 16 <= CUTF) {
#pragma unroll
        for (int q = 0; q < 4; q++) {
            float4 t = *(const float4*)(w + f0 + 4 * q);
            v[4 * q] = t.x; v[4 * q + 1] = t.y; v[4 * q + 2] = t.z; v[4 * q + 3] = t.w;
        }
    } else {
#pragma unroll
        for (int j = 0; j < 16; j++) {
            int f = f0 + j;
            v[j] = (ov && f < CUTF) ? w[f] : 0.f;
        }
    }
    u32 hh[8];
#pragma unroll
    for (int j = 0; j < 8; j++)
        hh[j] = pack2(sgn * v[2 * j], sgn * v[2 * j + 1]);
    u32 off = (u32)o2 * RSB + part * 32;
    asm volatile("st.shared.v4.b32 [%0], {%1,%2,%3,%4};"
                 :: "r"(Bs + off), "r"(hh[0]), "r"(hh[1]), "r"(hh[2]), "r"(hh[3]));
    asm volatile("st.shared.v4.b32 [%0], {%1,%2,%3,%4};"
                 :: "r"(Bs + off + 16), "r"(hh[4]), "r"(hh[5]), "r"(hh[6]), "r"(hh[7]));
}

#define NCH2 14
__global__ __launch_bounds__(256, 2) void k_g2(const float* __restrict__ Wr,
                                               const float* __restrict__ Wi,
                                               const float* __restrict__ br,
                                               const float* __restrict__ bi) {
    extern __shared__ char smraw[];
    u32 smb = s2u(smraw);
    const int tid = threadIdx.x, lane = tid & 31, warp = tid >> 5;
    const int wm = warp >> 2, wn = warp & 3;
    const int cidx = blockIdx.z, mBase = blockIdx.y * 128, nBase = blockIdx.x * 128;
    const int nv = 800 - nBase > 128 ? 128 : 800 - nBase;
    const char* gA = (const char*)(d_X + ((size_t)cidx * BATCH + mBase) * KX);
    float acc[4][4][4] = {};

    cp_tile(smb + 0 * TB, gA, KX * 2, 0, tid);
    cp_commit();
    build_w2(Wr, Wi, cidx, nBase, 0, smb + 1 * TB, tid);
    for (int ch = 0; ch < NCH2; ch++) {
        u32 buf = smb + (ch & 1) * 2 * TB;
        if (ch + 1 < NCH2) {
            u32 nb = smb + ((ch + 1) & 1) * 2 * TB;
            cp_tile(nb + 0 * TB, gA, KX * 2, (ch + 1) * 64, tid);
            cp_commit();
            build_w2(Wr, Wi, cidx, nBase, ch + 1, nb + 1 * TB, tid);
            cp_wait1();
        } else {
            cp_wait0();
        }
        __syncthreads();
        compute_chunk(acc, buf, buf + TB, wm, wn, lane, nv);
        __syncthreads();
    }
    const int g = lane >> 2, iq = lane & 3;
    const float* brp = br + (size_t)cidx * FOUT;
    const float* bip = bi + (size_t)cidx * FOUT;
#pragma unroll
    for (int mt = 0; mt < 4; mt++) {
        int row = mBase + wm * 64 + mt * 16 + g;
        size_t r0 = ((size_t)cidx * BATCH + row) * KS;
        size_t r1 = r0 + 8 * (size_t)KS;
#pragma unroll
        for (int nt = 0; nt < 4; nt++) {
            int col = nBase + wn * 32 + nt * 8 + 2 * iq;   // even
            if (col < 800) {
                int o = col >> 1;
                float vr = brp[o], vi = bip[o];
                float* cc = acc[mt][nt];
                float Re0 = cc[0] + vr, Im0 = cc[1] + vi;
                float Re1 = cc[2] + vr, Im1 = cc[3] + vi;
                bool oe = (o & 1) == 0;
                // S-group: even o -> +Re ; odd o -> -Im.  D-group: even -> +Im ; odd -> -Re
                d_OS[r0 + o] = __float2half_rn(oe ? Re0 : -Im0);
                d_OD[r0 + o] = __float2half_rn(oe ? Im0 : -Re0);
                d_OS[r1 + o] = __float2half_rn(oe ? Re1 : -Im1);
                d_OD[r1 + o] = __float2half_rn(oe ? Im1 : -Re1);
            }
        }
    }
}

// ---------------- stage 3: irfft halves (S and D GEMMs) ----------------------
#define NCH3 14
__global__ __launch_bounds__(256, 2) void k_g3() {
    extern __shared__ char smraw[];
    u32 smb = s2u(smraw);
    const int tid = threadIdx.x, lane = tid & 31, warp = tid >> 5;
    const int wm = warp >> 2, wn = warp & 3;
    const int cidx = blockIdx.z, mBase = blockIdx.y * 128;
    const int sel = blockIdx.x >= 3;                 // 0=S, 1=D
    const int nBase = (blockIdx.x - (sel ? 3 : 0)) * 128;
    const int nv = 361 - nBase > 128 ? 128 : 361 - nBase;
    const __half* Asrc = sel ? d_OD : d_OS;
    const char* gA = (const char*)(Asrc + ((size_t)cidx * BATCH + mBase) * KS);
    const char* gB = (const char*)(d_G + (size_t)sel * NU * KS + (size_t)nBase * KS);
    float acc[4][4][4] = {};

    cp_tile(smb + 0 * TB, gA, KS * 2, 0, tid);
    cp_tile(smb + 1 * TB, gB, KS * 2, 0, tid);
    cp_commit();
    for (int ch = 0; ch < NCH3; ch++) {
        u32 buf = smb + (ch & 1) * 2 * TB;
        if (ch + 1 < NCH3) {
            u32 nb = smb + ((ch + 1) & 1) * 2 * TB;
            int kb = (ch + 1) * 64;
            cp_tile(nb + 0 * TB, gA, KS * 2, kb, tid);
            cp_tile(nb + 1 * TB, gB, KS * 2, kb, tid);
            cp_commit();
            cp_wait1();
        } else {
            cp_wait0();
        }
        __syncthreads();
        compute_chunk(acc, buf, buf + TB, wm, wn, lane, nv);
        __syncthreads();
    }
    __half* dst = sel ? d_D : d_S;
    const int g = lane >> 2, iq = lane & 3;
#pragma unroll
    for (int mt = 0; mt < 4; mt++) {
        int row = mBase + wm * 64 + mt * 16 + g;
        __half* y0 = dst + ((size_t)cidx * BATCH + row) * NU;
        __half* y1 = y0 + 8 * (size_t)NU;
#pragma unroll
        for (int nt = 0; nt < 4; nt++) {
            int col = nBase + wn * 32 + nt * 8 + 2 * iq;
            if (col < 361) {
                float* cc = acc[mt][nt];
                *(u32*)(y0 + col) = pack2(cc[0], cc[1]);
                *(u32*)(y1 + col) = pack2(cc[2], cc[3]);
            }
        }
    }
}

// ---------------- transpose out: combine S/D, de-normalize -------------------
__global__ void k_transpose_out(float* __restrict__ out) {
    __shared__ float sm[32][33];
    int b = blockIdx.z;
    int c0 = blockIdx.x * 32, t0 = blockIdx.y * 32;
    int tx = threadIdx.x, ty = threadIdx.y;
#pragma unroll
    for (int i = 0; i < 4; i++) {
        int c = c0 + ty + i * 8;
        int t = t0 + tx;
        float v = 0.f;
        if (c < CH && t < SEQ) {
            int u = (t <= 360) ? t : (720 - t);
            float sg = (t <= 360) ? 1.f : -1.f;
            size_t base = ((size_t)c * BATCH + b) * NU + u;
            v = __half2float(d_S[base]) + sg * __half2float(d_D[base]);
        }
        sm[ty + i * 8][tx] = v;
    }
    __syncthreads();
#pragma unroll
    for (int i = 0; i < 4; i++) {
        int t = t0 + ty + i * 8;
        int c = c0 + tx;
        if (t < SEQ && c < CH) {
            float v = sm[tx][ty + i * 8];
            out[(size_t)b * SEQ * CH + (size_t)t * CH + c] =
                v * d_stdev[b * CH + c] + d_mean[b * CH + c];
        }
    }
}

// ---------------- launch -----------------------------------------------------
extern "C" void kernel_launch(void* const* d_in, const int* in_sizes, int n_in,
                              void* d_out, int out_size) {
    const float* x_enc = (const float*)d_in[0];
    const float* Wr = (const float*)d_in[4];
    const float* Wi = (const float*)d_in[5];
    const float* br = (const float*)d_in[6];
    const float* bi = (const float*)d_in[7];
    float* out = (float*)d_out;

    static int attrDone = 0;
    if (!attrDone) {
        cudaFuncSetAttribute(k_g1, cudaFuncAttributeMaxDynamicSharedMemorySize, SMEM_BYTES);
        cudaFuncSetAttribute(k_g2, cudaFuncAttributeMaxDynamicSharedMemorySize, SMEM_BYTES);
        cudaFuncSetAttribute(k_g3, cudaFuncAttributeMaxDynamicSharedMemorySize, SMEM_BYTES);
        attrDone = 1;
    }

    k_init<<<1344, 256>>>();
    k_stats<<<dim3(2, BATCH), 256>>>(x_enc);
    k_prep<<<dim3(11, 12, BATCH), dim3(32, 8)>>>(x_enc);
    k_g1<<<dim3(4, 2, CH), 256, SMEM_BYTES>>>();
    k_g2<<<dim3(7, 2, CH), 256, SMEM_BYTES>>>(Wr, Wi, br, bi);
    k_g3<<<dim3(6, 2, CH), 256, SMEM_BYTES>>>();
    k_transpose_out<<<dim3(11, 23, BATCH), dim3(32, 8)>>>(out);
}

// round 16
// speedup vs baseline: 2.1872x; 1.0980x over previous
#include <cuda_runtime.h>
#include <cuda_fp16.h>
#include <math.h>
#include <stdint.h>

#define BATCH 256
#define SEQ   720
#define CH    321
#define CUTF  200
#define FOUT  400

#define KU  384   // padded half-length K (361 -> 384) for stage 1
#define KX  448   // stage2 K: [Re 224 | Im 224]
#define KS  448   // stage3 K per half (400 -> 448)
#define NU  384   // stage3 N (u: 361 -> 384)

#define RSB 80            // smem row stride bytes (32 fp16 + 16 pad)
#define TB  (128 * RSB)   // one tile: 10240 B
#define SMEM_BYTES (4 * TB)

typedef unsigned int u32;
typedef uint16_t u16;

// ---------------- device scratch ---------------------------------------------
__device__ __align__(256) __half d_E1[(size_t)512 * KU];         // [cos f<256 | -sin]
__device__ __align__(256) __half d_G[(size_t)2 * NU * KS];       // Gs, Gd
__device__ __align__(256) __half d_xe[(size_t)CH * BATCH * (2 * KU)];  // [xe 384 | xo 384]
__device__ __align__(256) __half d_X[(size_t)CH * BATCH * KX];   // [Re 224 | Im 224]
__device__ __align__(256) __half d_OS[(size_t)CH * BATCH * KS];  // S-group columns
__device__ __align__(256) __half d_OD[(size_t)CH * BATCH * KS];  // D-group columns
__device__ __align__(256) __half d_S[(size_t)CH * BATCH * NU];
__device__ __align__(256) __half d_D[(size_t)CH * BATCH * NU];
__device__ float d_mean[BATCH * CH];
__device__ float d_stdev[BATCH * CH];
__device__ float d_invstd[BATCH * CH];

// ---------------- helpers ----------------------------------------------------
__device__ __forceinline__ u32 s2u(const void* p) {
    u32 a;
    asm("{ .reg .u64 t; cvta.to.shared.u64 t, %1; cvt.u32.u64 %0, t; }" : "=r"(a) : "l"(p));
    return a;
}
__device__ __forceinline__ void cpa16(u32 dst, const void* src) {
    asm volatile("cp.async.ca.shared.global [%0], [%1], 16;" :: "r"(dst), "l"(src));
}
__device__ __forceinline__ void cp_commit() { asm volatile("cp.async.commit_group;"); }
__device__ __forceinline__ void cp_wait1() { asm volatile("cp.async.wait_group 1;"); }
__device__ __forceinline__ void cp_wait0() { asm volatile("cp.async.wait_group 0;"); }
__device__ __forceinline__ void ldsm4(u32 a[4], u32 addr) {
    asm volatile("ldmatrix.sync.aligned.m8n8.x4.shared.b16 {%0,%1,%2,%3}, [%4];"
                 : "=r"(a[0]), "=r"(a[1]), "=r"(a[2]), "=r"(a[3]) : "r"(addr));
}
__device__ __forceinline__ void mma16816(float c[4], const u32 a[4], u32 b0, u32 b1) {
    asm volatile(
        "mma.sync.aligned.m16n8k16.row.col.f32.f16.f16.f32 "
        "{%0,%1,%2,%3},{%4,%5,%6,%7},{%8,%9},{%0,%1,%2,%3};"
        : "+f"(c[0]), "+f"(c[1]), "+f"(c[2]), "+f"(c[3])
        : "r"(a[0]), "r"(a[1]), "r"(a[2]), "r"(a[3]), "r"(b0), "r"(b1));
}
__device__ __forceinline__ u16 f2h(float v) { return __half_as_ushort(__float2half_rn(v)); }
__device__ __forceinline__ u32 pack2(float a, float b) {
    return (u32)f2h(a) | ((u32)f2h(b) << 16);
}

// cp.async one 128x32fp16 tile (64B/row) into padded smem; 256 threads
__device__ __forceinline__ void cp_tile(u32 smDst, const char* gSrc, int rowStrideBytes,
                                        int kByteOff, int tid) {
    int row = tid >> 1, seg = (tid & 1) * 32;
    const char* s = gSrc + (size_t)row * rowStrideBytes + kByteOff + seg;
    u32 d = smDst + row * RSB + seg;
    cpa16(d, s);
    cpa16(d + 16, s + 16);
}

// one 32-K chunk, single-product fp16; 8 warps (2x4), warp tile 64x32.
__device__ __forceinline__ void compute_chunk(float acc[4][4][4], u32 a_b, u32 b_b,
                                              int wm, int wn, int lane, int nv) {
    if (wn * 32 >= nv) return;
    const int rsel = lane & 15;
    const int kbh = (lane >> 4) * 16;
    const u32 aBase = a_b + (u32)(wm * 64 + rsel) * RSB + kbh;
    const u32 bBase = b_b + (u32)(wn * 32 + rsel) * RSB + kbh;
    const bool nv1 = (wn * 32 + 16) < nv;

    u32 b0[2][4], b1[2][4];
    ldsm4(b0[0], bBase);
    if (nv1) ldsm4(b0[1], bBase + 16 * RSB);
    u32 a[2][4];
    ldsm4(a[0], aBase);

#pragma unroll
    for (int mt = 0; mt < 4; mt++) {
        if (mt < 3) ldsm4(a[(mt + 1) & 1], aBase + (u32)(mt + 1) * 16 * RSB);
        else        ldsm4(a[(mt + 1) & 1], aBase + 32);
        if (mt == 1) {
            ldsm4(b1[0], bBase + 32);
            if (nv1) ldsm4(b1[1], bBase + 16 * RSB + 32);
        }
        const u32* av = a[mt & 1];
#pragma unroll
        for (int nt = 0; nt < 4; nt++) {
            if (wn * 32 + nt * 8 < nv)
                mma16816(acc[mt][nt], av, b0[nt >> 1][nt & 1], b0[nt >> 1][(nt & 1) + 2]);
        }
    }
#pragma unroll
    for (int mt = 0; mt < 4; mt++) {
        if (mt < 3) ldsm4(a[(mt + 1) & 1], aBase + (u32)(mt + 1) * 16 * RSB + 32);
        const u32* av = a[mt & 1];
#pragma unroll
        for (int nt = 0; nt < 4; nt++) {
            if (wn * 32 + nt * 8 < nv)
                mma16816(acc[mt][nt], av, b1[nt >> 1][nt & 1], b1[nt >> 1][(nt & 1) + 2]);
        }
    }
}

// ---------------- table init (one sincospif fills two entries) ---------------
__global__ void k_init2() {
    int idx = blockIdx.x * 256 + threadIdx.x;
    if (idx < 256 * KU) {
        int f = idx / KU, u = idx - f * KU;
        float vc = 0.f, vs = 0.f;
        if (f < CUTF && u <= 360) {
            int m = (f * u) % 720;
            float s, c;
            sincospif((float)m * (1.0f / 360.0f), &s, &c);
            vc = c; vs = -s;
        }
        d_E1[idx] = __float2half_rn(vc);
        d_E1[(size_t)256 * KU + idx] = __float2half_rn(vs);
    }
    if (idx < NU * KS) {
        int u = idx / KS, k = idx - u * KS;
        float gs = 0.f, gd = 0.f;
        if (k < 2 * CUTF && u <= 360) {
            int m = (k * u) % 1440;
            float s, c;
            sincospif((float)m * (1.0f / 720.0f), &s, &c);
            float sc = (k == 0) ? (1.0f / 720.0f) : (1.0f / 360.0f);
            bool ke = (k & 1) == 0;
            gs = ke ? sc * c : -sc * s;
            gd = ke ? -sc * s : sc * c;
        }
        d_G[idx] = __float2half_rn(gs);
        d_G[(size_t)NU * KS + idx] = __float2half_rn(gd);
    }
}

// ---------------- fused stats + fold + transpose -----------------------------
// block: 32 channels x one batch. pass 1: mean/std. pass 2: 12 u-tiles.
__global__ void k_prep2(const float* __restrict__ x) {
    __shared__ float rs[8][33], rss[8][33];
    __shared__ float smean[33], sinv[33];
    __shared__ float sa[32][33], sb[32][33];
    const int b = blockIdx.y;
    const int c0 = blockIdx.x * 32;
    const int tx = threadIdx.x, ty = threadIdx.y;
    const int c = c0 + tx;
    const bool cv = (c < CH);
    const float* xb = x + (size_t)b * SEQ * CH;

    float s = 0.f, ss = 0.f;
    for (int t = ty; t < SEQ; t += 8) {
        float v = cv ? xb[(size_t)t * CH + c] : 0.f;
        s += v;
        ss += v * v;
    }
    rs[ty][tx] = s;
    rss[ty][tx] = ss;
    __syncthreads();
    if (ty == 0) {
        float S = 0.f, SS = 0.f;
#pragma unroll
        for (int j = 0; j < 8; j++) { S += rs[j][tx]; SS += rss[j][tx]; }
        float mean = S * (1.0f / SEQ);
        float var = (SS - S * mean) * (1.0f / (SEQ - 1));
        float sd = sqrtf(var + 1e-5f);
        float inv = 1.0f / sd;
        smean[tx] = mean;
        sinv[tx] = inv;
        if (cv) {
            d_mean[b * CH + c] = mean;
            d_stdev[b * CH + c] = sd;
            d_invstd[b * CH + c] = inv;
        }
    }
    __syncthreads();
    const float mean = smean[tx], inv = sinv[tx];

    for (int u0 = 0; u0 < 384; u0 += 32) {
#pragma unroll
        for (int i = 0; i < 4; i++) {
            int u = u0 + ty + i * 8;
            float va = 0.f, vb = 0.f;
            if (cv) {
                if (u < SEQ) va = (xb[(size_t)u * CH + c] - mean) * inv;
                if (u >= 1 && u <= 359) vb = (xb[(size_t)(720 - u) * CH + c] - mean) * inv;
            }
            sa[ty + i * 8][tx] = va;
            sb[ty + i * 8][tx] = vb;
        }
        __syncthreads();
#pragma unroll
        for (int i = 0; i < 4; i++) {
            int cc = c0 + ty + i * 8;
            int u = u0 + tx;
            if (cc < CH && u <= 360) {
                float xnu = sa[tx][ty + i * 8];
                float pa = sb[tx][ty + i * 8];
                bool pv = (u >= 1 && u <= 359);
                float xe = xnu + pa;
                float xo = pv ? (xnu - pa) : 0.f;
                size_t base = ((size_t)cc * BATCH + b) * (2 * KU);
                d_xe[base + u] = __float2half_rn(xe);
                d_xe[base + KU + u] = __float2half_rn(xo);
            }
        }
        __syncthreads();
    }
}

// ---------------- stage 1: DFT (two half-GEMMs: Re over xe, Im over xo) ------
#define NCH1 12
__global__ __launch_bounds__(256, 2) void k_g1() {
    extern __shared__ char smraw[];
    u32 smb = s2u(smraw);
    const int tid = threadIdx.x, lane = tid & 31, warp = tid >> 5;
    const int wm = warp >> 2, wn = warp & 3;
    const int cidx = blockIdx.z, mBase = blockIdx.y * 128;
    const int half = blockIdx.x >> 1;
    const int nBase = (blockIdx.x & 1) * 128;
    const int nv = CUTF - nBase > 128 ? 128 : CUTF - nBase;
    const char* gA = (const char*)(d_xe + ((size_t)cidx * BATCH + mBase) * (2 * KU) + half * KU);
    const char* gB = (const char*)(d_E1 + (size_t)(half * 256 + nBase) * KU);
    float acc[4][4][4] = {};

    cp_tile(smb + 0 * TB, gA, 2 * KU * 2, 0, tid);
    cp_tile(smb + 1 * TB, gB, KU * 2, 0, tid);
    cp_commit();
    for (int ch = 0; ch < NCH1; ch++) {
        u32 buf = smb + (ch & 1) * 2 * TB;
        if (ch + 1 < NCH1) {
            u32 nb = smb + ((ch + 1) & 1) * 2 * TB;
            int kb = (ch + 1) * 64;
            cp_tile(nb + 0 * TB, gA, 2 * KU * 2, kb, tid);
            cp_tile(nb + 1 * TB, gB, KU * 2, kb, tid);
            cp_commit();
            cp_wait1();
        } else {
            cp_wait0();
        }
        __syncthreads();
        compute_chunk(acc, buf, buf + TB, wm, wn, lane, nv);
        __syncthreads();
    }
    const int g = lane >> 2, iq = lane & 3;
    const int regionOff = half * 224;
#pragma unroll
    for (int mt = 0; mt < 4; mt++) {
        int row = mBase + wm * 64 + mt * 16 + g;
        size_t b0 = ((size_t)cidx * BATCH + row) * KX + regionOff;
        size_t b1 = b0 + 8 * (size_t)KX;
#pragma unroll
        for (int nt = 0; nt < 4; nt++) {
            int f = nBase + wn * 32 + nt * 8 + 2 * iq;
            if (f < CUTF) {
                float* cc = acc[mt][nt];
                *(u32*)(d_X + b0 + f) = pack2(cc[0], cc[1]);
                *(u32*)(d_X + b1 + f) = pack2(cc[2], cc[3]);
            }
        }
    }
}

// ---------------- stage 2: complex mixer -------------------------------------
__device__ __forceinline__ void build_w2(const float* __restrict__ Wr,
                                         const float* __restrict__ Wi,
                                         int cidx, int nBase, int ch,
                                         u32 Bs, int tid) {
    int o2 = tid >> 1;
    int part = tid & 1;
    int o = (nBase >> 1) + (o2 >> 1);
    int p = o2 & 1;
    int k20 = ch * 32 + part * 16;
    bool reg = (ch < 7);
    int f0 = k20 - (reg ? 0 : 224);
    const bool ov = (o < FOUT);
    const float* wsrc;
    float sgn;
    if (reg) { wsrc = p ? Wi : Wr; sgn = 1.f; }
    else     { wsrc = p ? Wr : Wi; sgn = p ? 1.f : -1.f; }
    const float* w = wsrc + ((size_t)cidx * FOUT + o) * CUTF;

    float v[16];
    if (ov && f0 + 16 <= CUTF) {
#pragma unroll
        for (int q = 0; q < 4; q++) {
            float4 t = *(const float4*)(w + f0 + 4 * q);
            v[4 * q] = t.x; v[4 * q + 1] = t.y; v[4 * q + 2] = t.z; v[4 * q + 3] = t.w;
        }
    } else {
#pragma unroll
        for (int j = 0; j < 16; j++) {
            int f = f0 + j;
            v[j] = (ov && f < CUTF) ? w[f] : 0.f;
        }
    }
    u32 hh[8];
#pragma unroll
    for (int j = 0; j < 8; j++)
        hh[j] = pack2(sgn * v[2 * j], sgn * v[2 * j + 1]);
    u32 off = (u32)o2 * RSB + part * 32;
    asm volatile("st.shared.v4.b32 [%0], {%1,%2,%3,%4};"
                 :: "r"(Bs + off), "r"(hh[0]), "r"(hh[1]), "r"(hh[2]), "r"(hh[3]));
    asm volatile("st.shared.v4.b32 [%0], {%1,%2,%3,%4};"
                 :: "r"(Bs + off + 16), "r"(hh[4]), "r"(hh[5]), "r"(hh[6]), "r"(hh[7]));
}

#define NCH2 14
__global__ __launch_bounds__(256, 2) void k_g2(const float* __restrict__ Wr,
                                               const float* __restrict__ Wi,
                                               const float* __restrict__ br,
                                               const float* __restrict__ bi) {
    extern __shared__ char smraw[];
    u32 smb = s2u(smraw);
    const int tid = threadIdx.x, lane = tid & 31, warp = tid >> 5;
    const int wm = warp >> 2, wn = warp & 3;
    const int cidx = blockIdx.z, mBase = blockIdx.y * 128, nBase = blockIdx.x * 128;
    const int nv = 800 - nBase > 128 ? 128 : 800 - nBase;
    const char* gA = (const char*)(d_X + ((size_t)cidx * BATCH + mBase) * KX);
    float acc[4][4][4] = {};

    cp_tile(smb + 0 * TB, gA, KX * 2, 0, tid);
    cp_commit();
    build_w2(Wr, Wi, cidx, nBase, 0, smb + 1 * TB, tid);
    for (int ch = 0; ch < NCH2; ch++) {
        u32 buf = smb + (ch & 1) * 2 * TB;
        if (ch + 1 < NCH2) {
            u32 nb = smb + ((ch + 1) & 1) * 2 * TB;
            cp_tile(nb + 0 * TB, gA, KX * 2, (ch + 1) * 64, tid);
            cp_commit();
            build_w2(Wr, Wi, cidx, nBase, ch + 1, nb + 1 * TB, tid);
            cp_wait1();
        } else {
            cp_wait0();
        }
        __syncthreads();
        compute_chunk(acc, buf, buf + TB, wm, wn, lane, nv);
        __syncthreads();
    }
    const int g = lane >> 2, iq = lane & 3;
    const float* brp = br + (size_t)cidx * FOUT;
    const float* bip = bi + (size_t)cidx * FOUT;
#pragma unroll
    for (int mt = 0; mt < 4; mt++) {
        int row = mBase + wm * 64 + mt * 16 + g;
        size_t r0 = ((size_t)cidx * BATCH + row) * KS;
        size_t r1 = r0 + 8 * (size_t)KS;
#pragma unroll
        for (int nt = 0; nt < 4; nt++) {
            int col = nBase + wn * 32 + nt * 8 + 2 * iq;
            if (col < 800) {
                int o = col >> 1;
                float vr = brp[o], vi = bip[o];
                float* cc = acc[mt][nt];
                float Re0 = cc[0] + vr, Im0 = cc[1] + vi;
                float Re1 = cc[2] + vr, Im1 = cc[3] + vi;
                bool oe = (o & 1) == 0;
                d_OS[r0 + o] = __float2half_rn(oe ? Re0 : -Im0);
                d_OD[r0 + o] = __float2half_rn(oe ? Im0 : -Re0);
                d_OS[r1 + o] = __float2half_rn(oe ? Re1 : -Im1);
                d_OD[r1 + o] = __float2half_rn(oe ? Im1 : -Re1);
            }
        }
    }
}

// ---------------- stage 3: irfft halves (S and D GEMMs) ----------------------
#define NCH3 14
__global__ __launch_bounds__(256, 2) void k_g3() {
    extern __shared__ char smraw[];
    u32 smb = s2u(smraw);
    const int tid = threadIdx.x, lane = tid & 31, warp = tid >> 5;
    const int wm = warp >> 2, wn = warp & 3;
    const int cidx = blockIdx.z, mBase = blockIdx.y * 128;
    const int sel = blockIdx.x >= 3;
    const int nBase = (blockIdx.x - (sel ? 3 : 0)) * 128;
    const int nv = 361 - nBase > 128 ? 128 : 361 - nBase;
    const __half* Asrc = sel ? d_OD : d_OS;
    const char* gA = (const char*)(Asrc + ((size_t)cidx * BATCH + mBase) * KS);
    const char* gB = (const char*)(d_G + (size_t)sel * NU * KS + (size_t)nBase * KS);
    float acc[4][4][4] = {};

    cp_tile(smb + 0 * TB, gA, KS * 2, 0, tid);
    cp_tile(smb + 1 * TB, gB, KS * 2, 0, tid);
    cp_commit();
    for (int ch = 0; ch < NCH3; ch++) {
        u32 buf = smb + (ch & 1) * 2 * TB;
        if (ch + 1 < NCH3) {
            u32 nb = smb + ((ch + 1) & 1) * 2 * TB;
            int kb = (ch + 1) * 64;
            cp_tile(nb + 0 * TB, gA, KS * 2, kb, tid);
            cp_tile(nb + 1 * TB, gB, KS * 2, kb, tid);
            cp_commit();
            cp_wait1();
        } else {
            cp_wait0();
        }
        __syncthreads();
        compute_chunk(acc, buf, buf + TB, wm, wn, lane, nv);
        __syncthreads();
    }
    __half* dst = sel ? d_D : d_S;
    const int g = lane >> 2, iq = lane & 3;
#pragma unroll
    for (int mt = 0; mt < 4; mt++) {
        int row = mBase + wm * 64 + mt * 16 + g;
        __half* y0 = dst + ((size_t)cidx * BATCH + row) * NU;
        __half* y1 = y0 + 8 * (size_t)NU;
#pragma unroll
        for (int nt = 0; nt < 4; nt++) {
            int col = nBase + wn * 32 + nt * 8 + 2 * iq;
            if (col < 361) {
                float* cc = acc[mt][nt];
                *(u32*)(y0 + col) = pack2(cc[0], cc[1]);
                *(u32*)(y1 + col) = pack2(cc[2], cc[3]);
            }
        }
    }
}

// ---------------- output: combine S/D for both t=u and t=720-u ---------------
__global__ void k_out(float* __restrict__ out) {
    __shared__ float sS[32][33], sD[32][33];
    const int b = blockIdx.z;
    const int c0 = blockIdx.x * 32, u0 = blockIdx.y * 32;
    const int tx = threadIdx.x, ty = threadIdx.y;
#pragma unroll
    for (int i = 0; i < 4; i++) {
        int cc = c0 + ty + i * 8;
        int u = u0 + tx;
        float vs = 0.f, vd = 0.f;
        if (cc < CH && u <= 360) {
            size_t base = ((size_t)cc * BATCH + b) * NU + u;
            vs = __half2float(d_S[base]);
            vd = __half2float(d_D[base]);
        }
        sS[ty + i * 8][tx] = vs;
        sD[ty + i * 8][tx] = vd;
    }
    __syncthreads();
    const int c = c0 + tx;
    float sd_ = 0.f, mn = 0.f;
    if (c < CH) { sd_ = d_stdev[b * CH + c]; mn = d_mean[b * CH + c]; }
    float* ob = out + (size_t)b * SEQ * CH;
#pragma unroll
    for (int i = 0; i < 4; i++) {
        int u = u0 + ty + i * 8;
        if (c < CH && u <= 360) {
            float S = sS[tx][ty + i * 8], D = sD[tx][ty + i * 8];
            ob[(size_t)u * CH + c] = (S + D) * sd_ + mn;          // t = u
            if (u >= 1 && u <= 359)
                ob[(size_t)(720 - u) * CH + c] = (S - D) * sd_ + mn;  // t = 720-u
        }
    }
}

// ---------------- launch -----------------------------------------------------
extern "C" void kernel_launch(void* const* d_in, const int* in_sizes, int n_in,
                              void* d_out, int out_size) {
    const float* x_enc = (const float*)d_in[0];
    const float* Wr = (const float*)d_in[4];
    const float* Wi = (const float*)d_in[5];
    const float* br = (const float*)d_in[6];
    const float* bi = (const float*)d_in[7];
    float* out = (float*)d_out;

    static int attrDone = 0;
    if (!attrDone) {
        cudaFuncSetAttribute(k_g1, cudaFuncAttributeMaxDynamicSharedMemorySize, SMEM_BYTES);
        cudaFuncSetAttribute(k_g2, cudaFuncAttributeMaxDynamicSharedMemorySize, SMEM_BYTES);
        cudaFuncSetAttribute(k_g3, cudaFuncAttributeMaxDynamicSharedMemorySize, SMEM_BYTES);
        attrDone = 1;
    }

    k_init2<<<672, 256>>>();
    k_prep2<<<dim3(11, BATCH), dim3(32, 8)>>>(x_enc);
    k_g1<<<dim3(4, 2, CH), 256, SMEM_BYTES>>>();
    k_g2<<<dim3(7, 2, CH), 256, SMEM_BYTES>>>(Wr, Wi, br, bi);
    k_g3<<<dim3(6, 2, CH), 256, SMEM_BYTES>>>();
    k_out<<<dim3(11, 12, BATCH), dim3(32, 8)>>>(out);
}

// round 17
// speedup vs baseline: 2.2054x; 1.0083x over previous
#include <cuda_runtime.h>
#include <cuda_fp16.h>
#include <math.h>
#include <stdint.h>

#define BATCH 256
#define SEQ   720
#define CH    321
#define CUTF  200
#define FOUT  400

#define KU  384   // padded half-length K (361 -> 384) for stage 1
#define KX  448   // stage2 K: [Re 224 | Im 224]
#define KS  448   // stage3 K per half (400 -> 448)
#define NU  384   // stage3 N (u: 361 -> 384)
#define W2R 896   // padded stage2 N rows (800 -> 896)

#define RSB 80            // smem row stride bytes (32 fp16 + 16 pad)
#define TB  (128 * RSB)   // one tile: 10240 B
#define SMEM_BYTES (4 * TB)

typedef unsigned int u32;
typedef uint16_t u16;

// ---------------- device scratch ---------------------------------------------
__device__ __align__(256) __half d_E1[(size_t)512 * KU];         // [cos f<256 | -sin]
__device__ __align__(256) __half d_G[(size_t)2 * NU * KS];       // Gs, Gd
__device__ __align__(256) __half d_W2[(size_t)CH * W2R * KS];    // stage2 weights
__device__ __align__(256) __half d_xe[(size_t)CH * BATCH * (2 * KU)];  // [xe | xo]
__device__ __align__(256) __half d_X[(size_t)CH * BATCH * KX];   // [Re 224 | Im 224]
__device__ __align__(256) __half d_OS[(size_t)CH * BATCH * KS];  // S-group columns
__device__ __align__(256) __half d_OD[(size_t)CH * BATCH * KS];  // D-group columns
__device__ __align__(256) __half d_S[(size_t)CH * BATCH * NU];
__device__ __align__(256) __half d_D[(size_t)CH * BATCH * NU];
__device__ float d_mean[BATCH * CH];
__device__ float d_stdev[BATCH * CH];
__device__ float d_invstd[BATCH * CH];

// ---------------- helpers ----------------------------------------------------
__device__ __forceinline__ u32 s2u(const void* p) {
    u32 a;
    asm("{ .reg .u64 t; cvta.to.shared.u64 t, %1; cvt.u32.u64 %0, t; }" : "=r"(a) : "l"(p));
    return a;
}
__device__ __forceinline__ void cpa16(u32 dst, const void* src) {
    asm volatile("cp.async.ca.shared.global [%0], [%1], 16;" :: "r"(dst), "l"(src));
}
__device__ __forceinline__ void cp_commit() { asm volatile("cp.async.commit_group;"); }
__device__ __forceinline__ void cp_wait1() { asm volatile("cp.async.wait_group 1;"); }
__device__ __forceinline__ void cp_wait0() { asm volatile("cp.async.wait_group 0;"); }
__device__ __forceinline__ void ldsm4(u32 a[4], u32 addr) {
    asm volatile("ldmatrix.sync.aligned.m8n8.x4.shared.b16 {%0,%1,%2,%3}, [%4];"
                 : "=r"(a[0]), "=r"(a[1]), "=r"(a[2]), "=r"(a[3]) : "r"(addr));
}
__device__ __forceinline__ void mma16816(float c[4], const u32 a[4], u32 b0, u32 b1) {
    asm volatile(
        "mma.sync.aligned.m16n8k16.row.col.f32.f16.f16.f32 "
        "{%0,%1,%2,%3},{%4,%5,%6,%7},{%8,%9},{%0,%1,%2,%3};"
        : "+f"(c[0]), "+f"(c[1]), "+f"(c[2]), "+f"(c[3])
        : "r"(a[0]), "r"(a[1]), "r"(a[2]), "r"(a[3]), "r"(b0), "r"(b1));
}
__device__ __forceinline__ u16 f2h(float v) { return __half_as_ushort(__float2half_rn(v)); }
__device__ __forceinline__ u32 pack2(float a, float b) {
    return (u32)f2h(a) | ((u32)f2h(b) << 16);
}

// cp.async one 128x32fp16 tile (64B/row) into padded smem; 256 threads
__device__ __forceinline__ void cp_tile(u32 smDst, const char* gSrc, int rowStrideBytes,
                                        int kByteOff, int tid) {
    int row = tid >> 1, seg = (tid & 1) * 32;
    const char* s = gSrc + (size_t)row * rowStrideBytes + kByteOff + seg;
    u32 d = smDst + row * RSB + seg;
    cpa16(d, s);
    cpa16(d + 16, s + 16);
}

// one 32-K chunk, single-product fp16; 8 warps (2x4), warp tile 64x32.
__device__ __forceinline__ void compute_chunk(float acc[4][4][4], u32 a_b, u32 b_b,
                                              int wm, int wn, int lane, int nv) {
    if (wn * 32 >= nv) return;
    const int rsel = lane & 15;
    const int kbh = (lane >> 4) * 16;
    const u32 aBase = a_b + (u32)(wm * 64 + rsel) * RSB + kbh;
    const u32 bBase = b_b + (u32)(wn * 32 + rsel) * RSB + kbh;
    const bool nv1 = (wn * 32 + 16) < nv;

    u32 b0[2][4], b1[2][4];
    ldsm4(b0[0], bBase);
    if (nv1) ldsm4(b0[1], bBase + 16 * RSB);
    u32 a[2][4];
    ldsm4(a[0], aBase);

#pragma unroll
    for (int mt = 0; mt < 4; mt++) {
        if (mt < 3) ldsm4(a[(mt + 1) & 1], aBase + (u32)(mt + 1) * 16 * RSB);
        else        ldsm4(a[(mt + 1) & 1], aBase + 32);
        if (mt == 1) {
            ldsm4(b1[0], bBase + 32);
            if (nv1) ldsm4(b1[1], bBase + 16 * RSB + 32);
        }
        const u32* av = a[mt & 1];
#pragma unroll
        for (int nt = 0; nt < 4; nt++) {
            if (wn * 32 + nt * 8 < nv)
                mma16816(acc[mt][nt], av, b0[nt >> 1][nt & 1], b0[nt >> 1][(nt & 1) + 2]);
        }
    }
#pragma unroll
    for (int mt = 0; mt < 4; mt++) {
        if (mt < 3) ldsm4(a[(mt + 1) & 1], aBase + (u32)(mt + 1) * 16 * RSB + 32);
        const u32* av = a[mt & 1];
#pragma unroll
        for (int nt = 0; nt < 4; nt++) {
            if (wn * 32 + nt * 8 < nv)
                mma16816(acc[mt][nt], av, b1[nt >> 1][nt & 1], b1[nt >> 1][(nt & 1) + 2]);
        }
    }
}

// ---------------- table init (one sincospif fills two entries) ---------------
__global__ void k_init2() {
    int idx = blockIdx.x * 256 + threadIdx.x;
    if (idx < 256 * KU) {
        int f = idx / KU, u = idx - f * KU;
        float vc = 0.f, vs = 0.f;
        if (f < CUTF && u <= 360) {
            int m = (f * u) % 720;
            float s, c;
            sincospif((float)m * (1.0f / 360.0f), &s, &c);
            vc = c; vs = -s;
        }
        d_E1[idx] = __float2half_rn(vc);
        d_E1[(size_t)256 * KU + idx] = __float2half_rn(vs);
    }
    if (idx < NU * KS) {
        int u = idx / KS, k = idx - u * KS;
        float gs = 0.f, gd = 0.f;
        if (k < 2 * CUTF && u <= 360) {
            int m = (k * u) % 1440;
            float s, c;
            sincospif((float)m * (1.0f / 720.0f), &s, &c);
            float sc = (k == 0) ? (1.0f / 720.0f) : (1.0f / 360.0f);
            bool ke = (k & 1) == 0;
            gs = ke ? sc * c : -sc * s;
            gd = ke ? -sc * s : sc * c;
        }
        d_G[idx] = __float2half_rn(gs);
        d_G[(size_t)NU * KS + idx] = __float2half_rn(gd);
    }
}

// ---------------- W2 precompute: interleaved fp16 weights --------------------
// W2[c][r][k2]: r<800, o=r>>1, p=r&1.
//   k2<224:  f=k2;     val = f<200 ? (p? Wi : Wr)[c][o][f] : 0
//   k2>=224: f=k2-224; val = f<200 ? (p? Wr[c][o][f] : -Wi[c][o][f]) : 0
__global__ void k_wprep(const float* __restrict__ Wr, const float* __restrict__ Wi) {
    size_t idx = (size_t)blockIdx.x * 256 + threadIdx.x;   // one per 8 k2
    const size_t total = (size_t)CH * W2R * (KS / 8);
    if (idx >= total) return;
    int k8 = (int)(idx % (KS / 8));
    size_t t = idx / (KS / 8);
    int r = (int)(t % W2R);
    int c = (int)(t / W2R);
    int k20 = k8 * 8;
    u32 hh[4] = {0, 0, 0, 0};
    if (r < 800) {
        int o = r >> 1, p = r & 1;
        bool reg = k20 < 224;
        int f0 = reg ? k20 : (k20 - 224);
        const float* w;
        float sgn;
        if (reg) { w = p ? Wi : Wr; sgn = 1.f; }
        else     { w = p ? Wr : Wi; sgn = p ? 1.f : -1.f; }
        const float* wp = w + ((size_t)c * FOUT + o) * CUTF;
        float v[8];
#pragma unroll
        for (int j = 0; j < 8; j++) {
            int f = f0 + j;
            v[j] = (f < CUTF) ? wp[f] : 0.f;
        }
#pragma unroll
        for (int j = 0; j < 4; j++)
            hh[j] = pack2(sgn * v[2 * j], sgn * v[2 * j + 1]);
    }
    *(uint4*)(d_W2 + ((size_t)c * W2R + r) * KS + k20) = make_uint4(hh[0], hh[1], hh[2], hh[3]);
}

// ---------------- fused stats + fold + transpose -----------------------------
__global__ void k_prep2(const float* __restrict__ x) {
    __shared__ float rs[8][33], rss[8][33];
    __shared__ float smean[33], sinv[33];
    __shared__ float sa[32][33], sb[32][33];
    const int b = blockIdx.y;
    const int c0 = blockIdx.x * 32;
    const int tx = threadIdx.x, ty = threadIdx.y;
    const int c = c0 + tx;
    const bool cv = (c < CH);
    const float* xb = x + (size_t)b * SEQ * CH;

    float s = 0.f, ss = 0.f;
    for (int t = ty; t < SEQ; t += 8) {
        float v = cv ? xb[(size_t)t * CH + c] : 0.f;
        s += v;
        ss += v * v;
    }
    rs[ty][tx] = s;
    rss[ty][tx] = ss;
    __syncthreads();
    if (ty == 0) {
        float S = 0.f, SS = 0.f;
#pragma unroll
        for (int j = 0; j < 8; j++) { S += rs[j][tx]; SS += rss[j][tx]; }
        float mean = S * (1.0f / SEQ);
        float var = (SS - S * mean) * (1.0f / (SEQ - 1));
        float sd = sqrtf(var + 1e-5f);
        float inv = 1.0f / sd;
        smean[tx] = mean;
        sinv[tx] = inv;
        if (cv) {
            d_mean[b * CH + c] = mean;
            d_stdev[b * CH + c] = sd;
            d_invstd[b * CH + c] = inv;
        }
    }
    __syncthreads();
    const float mean = smean[tx], inv = sinv[tx];

    for (int u0 = 0; u0 < 384; u0 += 32) {
#pragma unroll
        for (int i = 0; i < 4; i++) {
            int u = u0 + ty + i * 8;
            float va = 0.f, vb = 0.f;
            if (cv) {
                if (u < SEQ) va = (xb[(size_t)u * CH + c] - mean) * inv;
                if (u >= 1 && u <= 359) vb = (xb[(size_t)(720 - u) * CH + c] - mean) * inv;
            }
            sa[ty + i * 8][tx] = va;
            sb[ty + i * 8][tx] = vb;
        }
        __syncthreads();
#pragma unroll
        for (int i = 0; i < 4; i++) {
            int cc = c0 + ty + i * 8;
            int u = u0 + tx;
            if (cc < CH && u <= 360) {
                float xnu = sa[tx][ty + i * 8];
                float pa = sb[tx][ty + i * 8];
                bool pv = (u >= 1 && u <= 359);
                float xe = xnu + pa;
                float xo = pv ? (xnu - pa) : 0.f;
                size_t base = ((size_t)cc * BATCH + b) * (2 * KU);
                d_xe[base + u] = __float2half_rn(xe);
                d_xe[base + KU + u] = __float2half_rn(xo);
            }
        }
        __syncthreads();
    }
}

// ---------------- stage 1: DFT (two half-GEMMs: Re over xe, Im over xo) ------
#define NCH1 12
__global__ __launch_bounds__(256, 2) void k_g1() {
    extern __shared__ char smraw[];
    u32 smb = s2u(smraw);
    const int tid = threadIdx.x, lane = tid & 31, warp = tid >> 5;
    const int wm = warp >> 2, wn = warp & 3;
    const int cidx = blockIdx.z, mBase = blockIdx.y * 128;
    const int half = blockIdx.x >> 1;
    const int nBase = (blockIdx.x & 1) * 128;
    const int nv = CUTF - nBase > 128 ? 128 : CUTF - nBase;
    const char* gA = (const char*)(d_xe + ((size_t)cidx * BATCH + mBase) * (2 * KU) + half * KU);
    const char* gB = (const char*)(d_E1 + (size_t)(half * 256 + nBase) * KU);
    float acc[4][4][4] = {};

    cp_tile(smb + 0 * TB, gA, 2 * KU * 2, 0, tid);
    cp_tile(smb + 1 * TB, gB, KU * 2, 0, tid);
    cp_commit();
    for (int ch = 0; ch < NCH1; ch++) {
        u32 buf = smb + (ch & 1) * 2 * TB;
        if (ch + 1 < NCH1) {
            u32 nb = smb + ((ch + 1) & 1) * 2 * TB;
            int kb = (ch + 1) * 64;
            cp_tile(nb + 0 * TB, gA, 2 * KU * 2, kb, tid);
            cp_tile(nb + 1 * TB, gB, KU * 2, kb, tid);
            cp_commit();
            cp_wait1();
        } else {
            cp_wait0();
        }
        __syncthreads();
        compute_chunk(acc, buf, buf + TB, wm, wn, lane, nv);
        __syncthreads();
    }
    const int g = lane >> 2, iq = lane & 3;
    const int regionOff = half * 224;
#pragma unroll
    for (int mt = 0; mt < 4; mt++) {
        int row = mBase + wm * 64 + mt * 16 + g;
        size_t b0 = ((size_t)cidx * BATCH + row) * KX + regionOff;
        size_t b1 = b0 + 8 * (size_t)KX;
#pragma unroll
        for (int nt = 0; nt < 4; nt++) {
            int f = nBase + wn * 32 + nt * 8 + 2 * iq;
            if (f < CUTF) {
                float* cc = acc[mt][nt];
                *(u32*)(d_X + b0 + f) = pack2(cc[0], cc[1]);
                *(u32*)(d_X + b1 + f) = pack2(cc[2], cc[3]);
            }
        }
    }
}

// ---------------- stage 2: complex mixer (pure GEMM over d_W2) ---------------
#define NCH2 14
__global__ __launch_bounds__(256, 2) void k_g2(const float* __restrict__ br,
                                               const float* __restrict__ bi) {
    extern __shared__ char smraw[];
    u32 smb = s2u(smraw);
    const int tid = threadIdx.x, lane = tid & 31, warp = tid >> 5;
    const int wm = warp >> 2, wn = warp & 3;
    const int cidx = blockIdx.z, mBase = blockIdx.y * 128, nBase = blockIdx.x * 128;
    const int nv = 800 - nBase > 128 ? 128 : 800 - nBase;
    const char* gA = (const char*)(d_X + ((size_t)cidx * BATCH + mBase) * KX);
    const char* gB = (const char*)(d_W2 + ((size_t)cidx * W2R + nBase) * KS);
    float acc[4][4][4] = {};

    cp_tile(smb + 0 * TB, gA, KX * 2, 0, tid);
    cp_tile(smb + 1 * TB, gB, KS * 2, 0, tid);
    cp_commit();
    for (int ch = 0; ch < NCH2; ch++) {
        u32 buf = smb + (ch & 1) * 2 * TB;
        if (ch + 1 < NCH2) {
            u32 nb = smb + ((ch + 1) & 1) * 2 * TB;
            int kb = (ch + 1) * 64;
            cp_tile(nb + 0 * TB, gA, KX * 2, kb, tid);
            cp_tile(nb + 1 * TB, gB, KS * 2, kb, tid);
            cp_commit();
            cp_wait1();
        } else {
            cp_wait0();
        }
        __syncthreads();
        compute_chunk(acc, buf, buf + TB, wm, wn, lane, nv);
        __syncthreads();
    }
    const int g = lane >> 2, iq = lane & 3;
    const float* brp = br + (size_t)cidx * FOUT;
    const float* bip = bi + (size_t)cidx * FOUT;
#pragma unroll
    for (int mt = 0; mt < 4; mt++) {
        int row = mBase + wm * 64 + mt * 16 + g;
        size_t r0 = ((size_t)cidx * BATCH + row) * KS;
        size_t r1 = r0 + 8 * (size_t)KS;
#pragma unroll
        for (int nt = 0; nt < 4; nt++) {
            int col = nBase + wn * 32 + nt * 8 + 2 * iq;
            if (col < 800) {
                int o = col >> 1;
                float vr = brp[o], vi = bip[o];
                float* cc = acc[mt][nt];
                float Re0 = cc[0] + vr, Im0 = cc[1] + vi;
                float Re1 = cc[2] + vr, Im1 = cc[3] + vi;
                bool oe = (o & 1) == 0;
                d_OS[r0 + o] = __float2half_rn(oe ? Re0 : -Im0);
                d_OD[r0 + o] = __float2half_rn(oe ? Im0 : -Re0);
                d_OS[r1 + o] = __float2half_rn(oe ? Re1 : -Im1);
                d_OD[r1 + o] = __float2half_rn(oe ? Im1 : -Re1);
            }
        }
    }
}

// ---------------- stage 3: irfft halves (S and D GEMMs) ----------------------
#define NCH3 14
__global__ __launch_bounds__(256, 2) void k_g3() {
    extern __shared__ char smraw[];
    u32 smb = s2u(smraw);
    const int tid = threadIdx.x, lane = tid & 31, warp = tid >> 5;
    const int wm = warp >> 2, wn = warp & 3;
    const int cidx = blockIdx.z, mBase = blockIdx.y * 128;
    const int sel = blockIdx.x >= 3;
    const int nBase = (blockIdx.x - (sel ? 3 : 0)) * 128;
    const int nv = 361 - nBase > 128 ? 128 : 361 - nBase;
    const __half* Asrc = sel ? d_OD : d_OS;
    const char* gA = (const char*)(Asrc + ((size_t)cidx * BATCH + mBase) * KS);
    const char* gB = (const char*)(d_G + (size_t)sel * NU * KS + (size_t)nBase * KS);
    float acc[4][4][4] = {};

    cp_tile(smb + 0 * TB, gA, KS * 2, 0, tid);
    cp_tile(smb + 1 * TB, gB, KS * 2, 0, tid);
    cp_commit();
    for (int ch = 0; ch < NCH3; ch++) {
        u32 buf = smb + (ch & 1) * 2 * TB;
        if (ch + 1 < NCH3) {
            u32 nb = smb + ((ch + 1) & 1) * 2 * TB;
            int kb = (ch + 1) * 64;
            cp_tile(nb + 0 * TB, gA, KS * 2, kb, tid);
            cp_tile(nb + 1 * TB, gB, KS * 2, kb, tid);
            cp_commit();
            cp_wait1();
        } else {
            cp_wait0();
        }
        __syncthreads();
        compute_chunk(acc, buf, buf + TB, wm, wn, lane, nv);
        __syncthreads();
    }
    __half* dst = sel ? d_D : d_S;
    const int g = lane >> 2, iq = lane & 3;
#pragma unroll
    for (int mt = 0; mt < 4; mt++) {
        int row = mBase + wm * 64 + mt * 16 + g;
        __half* y0 = dst + ((size_t)cidx * BATCH + row) * NU;
        __half* y1 = y0 + 8 * (size_t)NU;
#pragma unroll
        for (int nt = 0; nt < 4; nt++) {
            int col = nBase + wn * 32 + nt * 8 + 2 * iq;
            if (col < 361) {
                float* cc = acc[mt][nt];
                *(u32*)(y0 + col) = pack2(cc[0], cc[1]);
                *(u32*)(y1 + col) = pack2(cc[2], cc[3]);
            }
        }
    }
}

// ---------------- output: combine S/D for both t=u and t=720-u ---------------
__global__ void k_out(float* __restrict__ out) {
    __shared__ float sS[32][33], sD[32][33];
    const int b = blockIdx.z;
    const int c0 = blockIdx.x * 32, u0 = blockIdx.y * 32;
    const int tx = threadIdx.x, ty = threadIdx.y;
#pragma unroll
    for (int i = 0; i < 4; i++) {
        int cc = c0 + ty + i * 8;
        int u = u0 + tx;
        float vs = 0.f, vd = 0.f;
        if (cc < CH && u <= 360) {
            size_t base = ((size_t)cc * BATCH + b) * NU + u;
            vs = __half2float(d_S[base]);
            vd = __half2float(d_D[base]);
        }
        sS[ty + i * 8][tx] = vs;
        sD[ty + i * 8][tx] = vd;
    }
    __syncthreads();
    const int c = c0 + tx;
    float sd_ = 0.f, mn = 0.f;
    if (c < CH) { sd_ = d_stdev[b * CH + c]; mn = d_mean[b * CH + c]; }
    float* ob = out + (size_t)b * SEQ * CH;
#pragma unroll
    for (int i = 0; i < 4; i++) {
        int u = u0 + ty + i * 8;
        if (c < CH && u <= 360) {
            float S = sS[tx][ty + i * 8], D = sD[tx][ty + i * 8];
            ob[(size_t)u * CH + c] = (S + D) * sd_ + mn;
            if (u >= 1 && u <= 359)
                ob[(size_t)(720 - u) * CH + c] = (S - D) * sd_ + mn;
        }
    }
}

// ---------------- launch -----------------------------------------------------
extern "C" void kernel_launch(void* const* d_in, const int* in_sizes, int n_in,
                              void* d_out, int out_size) {
    const float* x_enc = (const float*)d_in[0];
    const float* Wr = (const float*)d_in[4];
    const float* Wi = (const float*)d_in[5];
    const float* br = (const float*)d_in[6];
    const float* bi = (const float*)d_in[7];
    float* out = (float*)d_out;

    static int attrDone = 0;
    if (!attrDone) {
        cudaFuncSetAttribute(k_g1, cudaFuncAttributeMaxDynamicSharedMemorySize, SMEM_BYTES);
        cudaFuncSetAttribute(k_g2, cudaFuncAttributeMaxDynamicSharedMemorySize, SMEM_BYTES);
        cudaFuncSetAttribute(k_g3, cudaFuncAttributeMaxDynamicSharedMemorySize, SMEM_BYTES);
        attrDone = 1;
    }

    k_init2<<<672, 256>>>();
    k_wprep<<<(int)(((size_t)CH * W2R * (KS / 8) + 255) / 256), 256>>>(Wr, Wi);
    k_prep2<<<dim3(11, BATCH), dim3(32, 8)>>>(x_enc);
    k_g1<<<dim3(4, 2, CH), 256, SMEM_BYTES>>>();
    k_g2<<<dim3(7, 2, CH), 256, SMEM_BYTES>>>(br, bi);
    k_g3<<<dim3(6, 2, CH), 256, SMEM_BYTES>>>();
    k_out<<<dim3(11, 12, BATCH), dim3(32, 8)>>>(out);
}